// round 12
// baseline (speedup 1.0000x reference)
#include <cuda_runtime.h>
#include <cuda_fp16.h>
#include <cstddef>
#include <math.h>

// Problem constants: N=4, H=W=256, C=8, CK=2, ITER=4, HID=16, C2=64.
#define NROW 1024            // n*256+h rows
#define TS 260               // per-transform smem stride (floats)

// Bank-conflict-free smem permutation for the radix-4 Stockham access sets.
// P(i) = i ^ ((i>>2)&28): invertible, preserves aligned 4-blocks.
__device__ __forceinline__ int PSW(int i) { return i ^ ((i >> 2) & 28); }

// ---------------- device scratch (no allocations allowed) ----------------
// gmat/dmat: [row][j][w][p]  p=half2 pair over k  (1024*8*256*4 half2 = 33.5MB each)
__device__ __align__(16) __half2 d_gmat[8388608];
__device__ __align__(16) __half2 d_dmat[8388608];
// filt: [wf][g][j][hf][q]  g=kk-half, q=0..3 -> kk=4g+q   (129*2*8*256*4 half2 = 8.45MB)
__device__ __align__(16) __half2 d_filt[(size_t)129 * 2 * 8 * 256 * 4];
__device__ __align__(16) float2 d_uf[(size_t)1024 * 129 * 8]; // [row][wf][c]
__device__ __align__(16) float  d_u[(size_t)1024 * 256 * 8];  // iterated field

__device__ __forceinline__ __half2 u2h(unsigned u) {
    __half2 h; *reinterpret_cast<unsigned*>(&h) = u; return h;
}
__device__ __forceinline__ unsigned h2u(__half2 h) {
    return *reinterpret_cast<unsigned*>(&h);
}

// ---------------- f32x2 packed math (sm_100+) ----------------
__device__ __forceinline__ unsigned long long pk2(float a, float b) {
    unsigned long long r;
    asm("mov.b64 %0, {%1, %2};" : "=l"(r) : "r"(__float_as_uint(a)), "r"(__float_as_uint(b)));
    return r;
}
__device__ __forceinline__ float2 upk2(unsigned long long v) {
    unsigned lo, hi;
    asm("mov.b64 {%0, %1}, %2;" : "=r"(lo), "=r"(hi) : "l"(v));
    return make_float2(__uint_as_float(lo), __uint_as_float(hi));
}
__device__ __forceinline__ unsigned long long fma2(unsigned long long a,
                                                   unsigned long long b,
                                                   unsigned long long c) {
    unsigned long long d;
    asm("fma.rn.f32x2 %0, %1, %2, %3;" : "=l"(d) : "l"(a), "l"(b), "l"(c));
    return d;
}

// ---------------- helpers ----------------
__device__ __forceinline__ float gelu_t(float x) {
    // exact tanhf — used in the iterated/output path only
    float inner = 0.7978845608028654f * (x + 0.044715f * x * x * x);
    return 0.5f * x * (1.0f + tanhf(inner));
}
__device__ __forceinline__ float gelu_a(float x) {
    // tanh.approx.f32 — setup MLPs only (error ~2^-11, below fp16 storage rounding)
    float inner = 0.7978845608028654f * (x + 0.044715f * x * x * x);
    float t;
    asm("tanh.approx.f32 %0, %1;" : "=f"(t) : "f"(inner));
    return 0.5f * x * (1.0f + t);
}

// MLP weights packed: w1[32]@0, b1[16]@32, w2[256]@48, b2[16]@304, w3[1024]@320, b3[64]@1344
__device__ __forceinline__ void load_mlp_w(float* dst,
    const float* w1, const float* b1, const float* w2, const float* b2,
    const float* w3, const float* b3, int tid, int nthr) {
    for (int i = tid; i < 32;   i += nthr) dst[i]        = w1[i];
    for (int i = tid; i < 16;   i += nthr) dst[32 + i]   = b1[i];
    for (int i = tid; i < 256;  i += nthr) dst[48 + i]   = w2[i];
    for (int i = tid; i < 16;   i += nthr) dst[304 + i]  = b2[i];
    for (int i = tid; i < 1024; i += nthr) dst[320 + i]  = w3[i];
    for (int i = tid; i < 64;   i += nthr) dst[1344 + i] = b3[i];
}

// 2-input MLP through the second gelu layer; f32x2 packed h2 layer + approx gelu.
// Outputs h2p[16]: each h2 value duplicated into a packed f32x2 multiplier.
__device__ __forceinline__ void mlp2_h2p(const float* __restrict__ Wm, float x0, float x1,
                                         unsigned long long* h2p) {
    unsigned long long h1p[16];
#pragma unroll
    for (int o = 0; o < 16; o++) {
        float h = gelu_a(fmaf(x0, Wm[o], fmaf(x1, Wm[16 + o], Wm[32 + o])));
        h1p[o] = pk2(h, h);
    }
#pragma unroll
    for (int o = 0; o < 16; o += 2) {
        const float2 bv = *reinterpret_cast<const float2*>(&Wm[304 + o]);
        unsigned long long acc = pk2(bv.x, bv.y);
#pragma unroll
        for (int i = 0; i < 16; i++) {
            float2 wv = *reinterpret_cast<const float2*>(&Wm[48 + i * 16 + o]);
            acc = fma2(h1p[i], pk2(wv.x, wv.y), acc);
        }
        float2 r = upk2(acc);
        float a0 = gelu_a(r.x), a1 = gelu_a(r.y);
        h2p[o]     = pk2(a0, a0);
        h2p[o + 1] = pk2(a1, a1);
    }
}

// In-smem Stockham radix-4 FFT, length 256, nf transforms at stride TS,
// all smem indices permuted by PSW (conflict-free). NT = threads cooperating.
// tw[t] = exp(-2*pi*i*t/256). sign=+1 forward, sign=-1 unnormalized inverse.
// Caller syncs before. Result ends in xr/xi (4 swaps).
template <int NT>
__device__ __forceinline__ void fft4_stages(float* xr, float* xi, float* yr, float* yi,
                                            const float2* __restrict__ tw,
                                            int nf, int tid, float sign) {
    float *ar = xr, *ai = xi, *br = yr, *bi = yi;
#pragma unroll
    for (int s = 0; s < 4; s++) {
        int m = 1 << (2 * s);            // 1,4,16,64
        for (int t0 = tid; t0 < nf * 64; t0 += NT) {
            int base = (t0 >> 6) * TS;
            int t = t0 & 63;
            int jm = t & ~(m - 1);
            int r  = t & (m - 1);
            float2 w1v = tw[jm];
            float2 w2v = tw[2 * jm];
            float w1r = w1v.x, w1i = sign * w1v.y;
            float w2r = w2v.x, w2i = sign * w2v.y;

            float Ar = ar[base + PSW(t)],       Ai = ai[base + PSW(t)];
            float Br = ar[base + PSW(t + 64)],  Bi = ai[base + PSW(t + 64)];
            float Cr = ar[base + PSW(t + 128)], Ci = ai[base + PSW(t + 128)];
            float Dr = ar[base + PSW(t + 192)], Di = ai[base + PSW(t + 192)];

            float s0r = Ar + Cr, s0i = Ai + Ci;
            float d0r = Ar - Cr, d0i = Ai - Ci;
            float s2r = Br + Dr, s2i = Bi + Di;
            float d1r = Br - Dr, d1i = Bi - Di;
            float s1r = w1r * d0r - w1i * d0i;
            float s1i = w1r * d0i + w1i * d0r;
            float er = sign * d1i, ei = -sign * d1r;
            float s3r = w1r * er - w1i * ei;
            float s3i = w1r * ei + w1i * er;

            float u0r = s0r - s2r, u0i = s0i - s2i;
            float u1r = s1r - s3r, u1i = s1i - s3i;
            float o2r = w2r * u0r - w2i * u0i;
            float o2i = w2r * u0i + w2i * u0r;
            float o3r = w2r * u1r - w2i * u1i;
            float o3i = w2r * u1i + w2i * u1r;

            if (s == 0) {
                // m=1: contiguous outputs -> one float4 store per array
                int o = base + PSW(4 * t);
                *reinterpret_cast<float4*>(br + o) =
                    make_float4(s0r + s2r, s1r + s3r, o2r, o3r);
                *reinterpret_cast<float4*>(bi + o) =
                    make_float4(s0i + s2i, s1i + s3i, o2i, o3i);
            } else {
                int o = 4 * jm + r;
                br[base + PSW(o)]         = s0r + s2r;
                bi[base + PSW(o)]         = s0i + s2i;
                br[base + PSW(o + m)]     = s1r + s3r;
                bi[base + PSW(o + m)]     = s1i + s3i;
                br[base + PSW(o + 2 * m)] = o2r;
                bi[base + PSW(o + 2 * m)] = o2i;
                br[base + PSW(o + 3 * m)] = o3r;
                bi[base + PSW(o + 3 * m)] = o3i;
            }
        }
        __syncthreads();
        float* tp;
        tp = ar; ar = br; br = tp;
        tp = ai; ai = bi; bi = tp;
    }
}

__device__ __forceinline__ void fill_tw(float2* tws, int tid, int nthr) {
    for (int t = tid; t < 128; t += nthr) {
        float s, c;
        sincospif((float)t * (1.0f / 128.0f), &s, &c);
        tws[t] = make_float2(c, -s);
    }
}

// ---- shared tail: pack du, forward rfft_W, write Uf (used by k_gdf and k_row) ----
__device__ __forceinline__ void fwd_rfft_store(float* xr, float* xi, float* yr, float* yi,
                                               const float2* tws, const float* du,
                                               float2* ufrow, int tid) {
    int pw = PSW(tid);
#pragma unroll
    for (int p = 0; p < 4; p++) {
        xr[p * TS + pw] = du[2 * p];
        xi[p * TS + pw] = du[2 * p + 1];
    }
    __syncthreads();
    fft4_stages<256>(xr, xi, yr, yi, tws, 4, tid, 1.0f);    // forward
    if (tid <= 128) {
        int k2 = tid, m2 = (256 - k2) & 255;
        int pk2i = PSW(k2), pm2 = PSW(m2);
#pragma unroll
        for (int p = 0; p < 4; p++) {
            float Zr = xr[p * TS + pk2i], Zi = xi[p * TS + pk2i];
            float Qr = xr[p * TS + pm2], Qi = xi[p * TS + pm2];
            float2 A = make_float2(0.5f * (Zr + Qr), 0.5f * (Zi - Qi));
            float2 B = make_float2(0.5f * (Zi + Qi), 0.5f * (Qr - Zr));
            ufrow[k2 * 8 + 2 * p]     = A;
            ufrow[k2 * 8 + 2 * p + 1] = B;
        }
    }
}

// ---------------- kernel A (fused): G/D MLPs + iteration-0 du + rfft_W -> Uf --------
// Thread w owns pixel (row, w): it computes the full fp32 D matrix for that pixel,
// so du = u @ D is formed in-register from fp32 values (no fp16 roundtrip, no
// re-read of dmat). This replaces the former k_row<0> launch entirely.
__global__ __launch_bounds__(256) void k_gdf(const float* __restrict__ kin,
    const float* __restrict__ uin,
    const float* gw1, const float* gb1, const float* gw2, const float* gb2,
    const float* gw3, const float* gb3,
    const float* dw1, const float* db1, const float* dw2, const float* db2,
    const float* dw3, const float* db3) {
    __shared__ float Wg[1408], Wd[1408];
    __shared__ __align__(16) float xr[4 * TS], xi[4 * TS], yr[4 * TS], yi[4 * TS];
    __shared__ float2 tws[128];
    int tid = threadIdx.x;
    load_mlp_w(Wg, gw1, gb1, gw2, gb2, gw3, gb3, tid, 256);
    load_mlp_w(Wd, dw1, db1, dw2, db2, dw3, db3, tid, 256);
    fill_tw(tws, tid, 256);
    __syncthreads();

    int row = blockIdx.x;       // n*256 + h
    int w   = tid;
    int pix = row * 256 + w;
    float x0 = kin[pix * 2 + 0];
    float x1 = kin[pix * 2 + 1];

    float uu[8];
    {
        const float4* up = (const float4*)(uin + (size_t)row * 2048 + w * 8);
        float4 a = up[0], b = up[1];
        uu[0] = a.x; uu[1] = a.y; uu[2] = a.z; uu[3] = a.w;
        uu[4] = b.x; uu[5] = b.y; uu[6] = b.z; uu[7] = b.w;
    }

    unsigned long long h2p[16];
    const float inv64 = 1.0f / 64.0f;
    float du[8];
#pragma unroll
    for (int kk = 0; kk < 8; kk++) du[kk] = 0.0f;

    // delta MLP: store fp16 D, accumulate fp32 du = u @ D
    mlp2_h2p(Wd, x0, x1, h2p);
#pragma unroll
    for (int j = 0; j < 8; j++) {
        uint4 pk;
        unsigned* pku = &pk.x;
        float uj = uu[j];
#pragma unroll
        for (int p = 0; p < 4; p++) {
            int jk0 = j * 8 + 2 * p;
            const float2 bv = *reinterpret_cast<const float2*>(&Wd[1344 + jk0]);
            unsigned long long acc = pk2(bv.x, bv.y);
#pragma unroll
            for (int i = 0; i < 16; i++) {
                float2 wv = *reinterpret_cast<const float2*>(&Wd[320 + i * 64 + jk0]);
                acc = fma2(h2p[i], pk2(wv.x, wv.y), acc);
            }
            float2 r = upk2(acc);
            float v0 = r.x * inv64, v1 = r.y * inv64;
            du[2 * p]     = fmaf(uj, v0, du[2 * p]);
            du[2 * p + 1] = fmaf(uj, v1, du[2 * p + 1]);
            pku[p] = h2u(__floats2half2_rn(v0, v1));
        }
        *reinterpret_cast<uint4*>(d_dmat + ((size_t)(row * 8 + j) * 256 + w) * 4) = pk;
    }
    // gamma MLP: store fp16 G
    mlp2_h2p(Wg, x0, x1, h2p);
#pragma unroll
    for (int j = 0; j < 8; j++) {
        uint4 pk;
        unsigned* pku = &pk.x;
#pragma unroll
        for (int p = 0; p < 4; p++) {
            int jk0 = j * 8 + 2 * p;
            const float2 bv = *reinterpret_cast<const float2*>(&Wg[1344 + jk0]);
            unsigned long long acc = pk2(bv.x, bv.y);
#pragma unroll
            for (int i = 0; i < 16; i++) {
                float2 wv = *reinterpret_cast<const float2*>(&Wg[320 + i * 64 + jk0]);
                acc = fma2(h2p[i], pk2(wv.x, wv.y), acc);
            }
            float2 r = upk2(acc);
            pku[p] = h2u(__floats2half2_rn(r.x * inv64, r.y * inv64));
        }
        *reinterpret_cast<uint4*>(d_gmat + ((size_t)(row * 8 + j) * 256 + w) * 4) = pk;
    }

    // forward rfft_W of du -> Uf (iteration 0 row pass)
    float2* ufrow = d_uf + (size_t)row * 129 * 8;
    fwd_rfft_store(xr, xi, yr, yi, tws, du, ufrow, tid);
}

// ---------------- kernel B: spectral filter (fp16, [wf][g][j][hf][q], f32x2 MLP) ----
// MLP input (kx, ky) = (wf, signed(hf)). Scale = 1/64 only; the 1/65536 FFT
// normalization is applied in k_col's store (fp16 would underflow).
__global__ __launch_bounds__(256) void k_filt(
    const float* rw1, const float* rb1, const float* rw2, const float* rb2,
    const float* rw3, const float* rb3,
    const float* iw1, const float* ib1, const float* iw2, const float* ib2,
    const float* iw3, const float* ib3) {
    __shared__ float Wr[1408], Wi[1408];
    int tid = threadIdx.x;
    load_mlp_w(Wr, rw1, rb1, rw2, rb2, rw3, rb3, tid, 256);
    load_mlp_w(Wi, iw1, ib1, iw2, ib2, iw3, ib3, tid, 256);
    __syncthreads();

    int wf = blockIdx.x;
    int hf = tid;
    float x0 = (float)wf;
    float x1 = (float)(hf < 128 ? hf : hf - 256);
    unsigned long long h2rp[16], h2ip[16];
    mlp2_h2p(Wr, x0, x1, h2rp);
    mlp2_h2p(Wi, x0, x1, h2ip);
    const float sc = 1.0f / 64.0f;
#pragma unroll
    for (int g = 0; g < 2; g++) {
#pragma unroll
        for (int j = 0; j < 8; j++) {
            uint4 pk;
            unsigned* pku = &pk.x;
#pragma unroll
            for (int qq = 0; qq < 2; qq++) {           // pairs (q=2qq, 2qq+1)
                int jk0 = j * 8 + 4 * g + 2 * qq;
                const float2 bvr = *reinterpret_cast<const float2*>(&Wr[1344 + jk0]);
                const float2 bvi = *reinterpret_cast<const float2*>(&Wi[1344 + jk0]);
                unsigned long long accr = pk2(bvr.x, bvr.y);
                unsigned long long acci = pk2(bvi.x, bvi.y);
#pragma unroll
                for (int i = 0; i < 16; i++) {
                    float2 wvr = *reinterpret_cast<const float2*>(&Wr[320 + i * 64 + jk0]);
                    float2 wvi = *reinterpret_cast<const float2*>(&Wi[320 + i * 64 + jk0]);
                    accr = fma2(h2rp[i], pk2(wvr.x, wvr.y), accr);
                    acci = fma2(h2ip[i], pk2(wvi.x, wvi.y), acci);
                }
                float2 rr = upk2(accr);
                float2 ri = upk2(acci);
                pku[2 * qq]     = h2u(__floats2half2_rn(rr.x * sc, ri.x * sc));
                pku[2 * qq + 1] = h2u(__floats2half2_rn(rr.y * sc, ri.y * sc));
            }
            size_t idx = ((((size_t)wf * 2 + g) * 8 + j) * 256 + hf) * 4;
            *reinterpret_cast<uint4*>(d_filt + idx) = pk;
        }
    }
}

// ---------------- row pass (iterations 1..) ----------------
// MODE 1: gu = irfft_W(Uf) ; u' = 2u + (gu-u)@G -> d_u ; du = u'@D ; rfft_W -> Uf
// MODE 2: gu = irfft_W(Uf) ; u' = 2u + (gu-u)@G ; out = gelu(u'+bias)
template <int MODE>
__global__ __launch_bounds__(256) void k_row(const float* __restrict__ uin,
                                             const float* __restrict__ bias,
                                             float* __restrict__ outp) {
    __shared__ __align__(16) float xr[4 * TS], xi[4 * TS], yr[4 * TS], yi[4 * TS];
    __shared__ float2 tws[128];

    int tid = threadIdx.x;
    int row = blockIdx.x;                       // n*256 + h
    fill_tw(tws, tid, 256);

    float2* ufrow = d_uf + (size_t)row * 129 * 8;
    const float* ubase = (uin != nullptr) ? uin : d_u;
    const float* urow  = ubase + (size_t)row * 2048;

    float unew[8];
    int w = tid;

    {
        // coalesced load of this thread's spectrum column (64B);
        // drop Im at DC/Nyquist (c2r semantics); Hermitian pack into xr/xi.
        int wfL = (tid <= 128) ? tid : 256 - tid;
        const float4* up = (const float4*)(ufrow + wfL * 8);
        float4 q0 = up[0], q1 = up[1], q2 = up[2], q3 = up[3];
        if (wfL == 0 || wfL == 128) {
            q0.y = 0.0f; q0.w = 0.0f; q1.y = 0.0f; q1.w = 0.0f;
            q2.y = 0.0f; q2.w = 0.0f; q3.y = 0.0f; q3.w = 0.0f;
        }
        float4 qs[4] = {q0, q1, q2, q3};
        int pt = PSW(tid);
        if (tid <= 128) {
#pragma unroll
            for (int p = 0; p < 4; p++) {
                xr[p * TS + pt] = qs[p].x - qs[p].w;   // A.x - B.y
                xi[p * TS + pt] = qs[p].y + qs[p].z;   // A.y + B.x
            }
        } else {
#pragma unroll
            for (int p = 0; p < 4; p++) {
                xr[p * TS + pt] = qs[p].x + qs[p].w;   // A.x + B.y
                xi[p * TS + pt] = qs[p].z - qs[p].y;   // B.x - A.y
            }
        }
        __syncthreads();
        fft4_stages<256>(xr, xi, yr, yi, tws, 4, tid, -1.0f);   // inverse (unnormalized)

        float gu[8], uu[8];
        int pw = PSW(w);
#pragma unroll
        for (int p = 0; p < 4; p++) {
            gu[2 * p]     = xr[p * TS + pw];
            gu[2 * p + 1] = xi[p * TS + pw];
        }
        {
            const float4* upu = (const float4*)(urow + w * 8);
            float4 a = upu[0], b = upu[1];
            uu[0] = a.x; uu[1] = a.y; uu[2] = a.z; uu[3] = a.w;
            uu[4] = b.x; uu[5] = b.y; uu[6] = b.z; uu[7] = b.w;
        }
        float tv[8];
#pragma unroll
        for (int j = 0; j < 8; j++) tv[j] = gu[j] - uu[j];
#pragma unroll
        for (int kk = 0; kk < 8; kk++) unew[kk] = 2.0f * uu[kk];
        const __half2* G = d_gmat + (size_t)row * 8 * 1024 + w * 4;
#pragma unroll
        for (int j = 0; j < 8; j++) {
            float tj = tv[j];
            uint4 raw = *reinterpret_cast<const uint4*>(G + j * 1024);
            float2 g0 = __half22float2(u2h(raw.x));
            float2 g1 = __half22float2(u2h(raw.y));
            float2 g2 = __half22float2(u2h(raw.z));
            float2 g3 = __half22float2(u2h(raw.w));
            unew[0] = fmaf(tj, g0.x, unew[0]); unew[1] = fmaf(tj, g0.y, unew[1]);
            unew[2] = fmaf(tj, g1.x, unew[2]); unew[3] = fmaf(tj, g1.y, unew[3]);
            unew[4] = fmaf(tj, g2.x, unew[4]); unew[5] = fmaf(tj, g2.y, unew[5]);
            unew[6] = fmaf(tj, g3.x, unew[6]); unew[7] = fmaf(tj, g3.y, unew[7]);
        }
        if (MODE == 2) {
            float4 o0, o1;
            o0.x = gelu_t(unew[0] + bias[0]);
            o0.y = gelu_t(unew[1] + bias[1]);
            o0.z = gelu_t(unew[2] + bias[2]);
            o0.w = gelu_t(unew[3] + bias[3]);
            o1.x = gelu_t(unew[4] + bias[4]);
            o1.y = gelu_t(unew[5] + bias[5]);
            o1.z = gelu_t(unew[6] + bias[6]);
            o1.w = gelu_t(unew[7] + bias[7]);
            float4* op = (float4*)(outp + (size_t)row * 2048 + w * 8);
            op[0] = o0; op[1] = o1;
            return;
        }
        // MODE 1: persist u'
        {
            float4 o0, o1;
            o0.x = unew[0]; o0.y = unew[1]; o0.z = unew[2]; o0.w = unew[3];
            o1.x = unew[4]; o1.y = unew[5]; o1.z = unew[6]; o1.w = unew[7];
            float4* op = (float4*)(d_u + (size_t)row * 2048 + w * 8);
            op[0] = o0; op[1] = o1;
        }
    }

    // du = unew @ D ; pack ; forward FFT ; unpack rfft ; write Uf
    {
        const __half2* D = d_dmat + (size_t)row * 8 * 1024 + w * 4;
        float du[8];
#pragma unroll
        for (int kk = 0; kk < 8; kk++) du[kk] = 0.0f;
#pragma unroll
        for (int j = 0; j < 8; j++) {
            float uj = unew[j];
            uint4 raw = *reinterpret_cast<const uint4*>(D + j * 1024);
            float2 g0 = __half22float2(u2h(raw.x));
            float2 g1 = __half22float2(u2h(raw.y));
            float2 g2 = __half22float2(u2h(raw.z));
            float2 g3 = __half22float2(u2h(raw.w));
            du[0] = fmaf(uj, g0.x, du[0]); du[1] = fmaf(uj, g0.y, du[1]);
            du[2] = fmaf(uj, g1.x, du[2]); du[3] = fmaf(uj, g1.y, du[3]);
            du[4] = fmaf(uj, g2.x, du[4]); du[5] = fmaf(uj, g2.y, du[5]);
            du[6] = fmaf(uj, g3.x, du[6]); du[7] = fmaf(uj, g3.y, du[7]);
        }
        __syncthreads();   // all gu reads of xr/xi complete
        fwd_rfft_store(xr, xi, yr, yi, tws, du, ufrow, tid);
    }
}

// ---------------- column pass: FFT_H, filter matvec, IFFT_H (in-place on Uf) ---------
// 512 threads: one butterfly per thread per stage; matvec split by kk-half.
// R10 form (21.9us). No reg cap (R8: caps spill); 256-thr/2-butterfly was slower (R11).
__global__ __launch_bounds__(512) void k_col() {
    __shared__ __align__(16) float xr[8 * TS], xi[8 * TS], yr[8 * TS], yi[8 * TS];
    __shared__ float2 tws[128];
    int tid = threadIdx.x;
    int wf = blockIdx.x % 129;
    int n  = blockIdx.x / 129;
    fill_tw(tws, tid, 512);

    float2* base = d_uf + ((size_t)n * 256 * 129 + wf) * 8;  // + h*129*8 + c
    for (int it = 0; it < 4; it++) {
        int idx = it * 512 + tid;
        int h = idx >> 3, c = idx & 7;
        float2 v = base[(size_t)h * 129 * 8 + c];
        int a = c * TS + PSW(h);
        xr[a] = v.x;
        xi[a] = v.y;
    }
    __syncthreads();
    fft4_stages<512>(xr, xi, yr, yi, tws, 8, tid, 1.0f);     // forward along H

    int hf = tid & 255;
    int g  = tid >> 8;          // kk-half
    int ph = PSW(hf);
    float vr[4], vi[4];
#pragma unroll
    for (int q = 0; q < 4; q++) { vr[q] = 0.0f; vi[q] = 0.0f; }
    const __half2* F = d_filt + (((size_t)wf * 2 + g) * 8 * 256 + hf) * 4;
#pragma unroll
    for (int j = 0; j < 8; j++) {
        float zr = xr[j * TS + ph], zi = xi[j * TS + ph];
        uint4 fa = *reinterpret_cast<const uint4*>(F + (size_t)j * 1024);
        const unsigned* fu = &fa.x;
#pragma unroll
        for (int q = 0; q < 4; q++) {
            float2 f = __half22float2(u2h(fu[q]));
            vr[q] = fmaf(zr, f.x, fmaf(-zi, f.y, vr[q]));
            vi[q] = fmaf(zr, f.y, fmaf(zi, f.x, vi[q]));
        }
    }
    __syncthreads();
#pragma unroll
    for (int q = 0; q < 4; q++) {
        int kk = 4 * g + q;
        yr[kk * TS + ph] = vr[q];
        yi[kk * TS + ph] = vi[q];
    }
    __syncthreads();
    fft4_stages<512>(yr, yi, xr, xi, tws, 8, tid, -1.0f);    // inverse (unnormalized)

    const float inv = 1.0f / 65536.0f;  // both inverse-FFT norms (kept out of fp16 filt)
    for (int it = 0; it < 4; it++) {
        int idx = it * 512 + tid;
        int h = idx >> 3, c = idx & 7;
        int a = c * TS + PSW(h);
        base[(size_t)h * 129 * 8 + c] = make_float2(yr[a] * inv, yi[a] * inv);
    }
}

// ---------------- launch ----------------
extern "C" void kernel_launch(void* const* d_in, const int* in_sizes, int n_in,
                              void* d_out, int out_size) {
    const float* u    = (const float*)d_in[0];
    const float* kk   = (const float*)d_in[1];
    const float* gW[6];  for (int i = 0; i < 6; i++) gW[i]  = (const float*)d_in[2 + i];
    const float* dW[6];  for (int i = 0; i < 6; i++) dW[i]  = (const float*)d_in[8 + i];
    const float* frW[6]; for (int i = 0; i < 6; i++) frW[i] = (const float*)d_in[14 + i];
    const float* fiW[6]; for (int i = 0; i < 6; i++) fiW[i] = (const float*)d_in[20 + i];
    const float* bias = (const float*)d_in[26];
    float* out = (float*)d_out;

    // fused: G/D MLPs + iteration-0 row pass (du + rfft_W -> Uf)
    k_gdf<<<NROW, 256>>>(kk, u,
        gW[0], gW[1], gW[2], gW[3], gW[4], gW[5],
        dW[0], dW[1], dW[2], dW[3], dW[4], dW[5]);
    k_filt<<<129, 256>>>(
        frW[0], frW[1], frW[2], frW[3], frW[4], frW[5],
        fiW[0], fiW[1], fiW[2], fiW[3], fiW[4], fiW[5]);

    for (int it = 0; it < 4; it++) {
        k_col<<<4 * 129, 512>>>();
        if (it < 3) {
            k_row<1><<<NROW, 256>>>(it == 0 ? u : nullptr, nullptr, nullptr);
        } else {
            k_row<2><<<NROW, 256>>>(nullptr, bias, out);
        }
    }
}

// round 13
// speedup vs baseline: 1.0270x; 1.0270x over previous
#include <cuda_runtime.h>
#include <cuda_fp16.h>
#include <cstddef>
#include <math.h>

// Problem constants: N=4, H=W=256, C=8, CK=2, ITER=4, HID=16, C2=64.
#define NROW 1024            // n*256+h rows
#define TS 260               // per-transform smem stride (floats)

// Bank-conflict-free smem permutation for the radix-4 Stockham access sets.
// P(i) = i ^ ((i>>2)&28): invertible, preserves aligned 4-blocks.
__device__ __forceinline__ int PSW(int i) { return i ^ ((i >> 2) & 28); }

// ---------------- device scratch (no allocations allowed) ----------------
// gmat/dmat: [row][j][w][p]  p=half2 pair over k  (1024*8*256*4 half2 = 33.5MB each)
__device__ __align__(16) __half2 d_gmat[8388608];
__device__ __align__(16) __half2 d_dmat[8388608];
// filt: [wf][g][j][hf][q]  g=kk-half, q=0..3 -> kk=4g+q   (129*2*8*256*4 half2 = 8.45MB)
__device__ __align__(16) __half2 d_filt[(size_t)129 * 2 * 8 * 256 * 4];
__device__ __align__(16) float2 d_uf[(size_t)1024 * 129 * 8]; // [row][wf][c]
__device__ __align__(16) float  d_u[(size_t)1024 * 256 * 8];  // iterated field

__device__ __forceinline__ __half2 u2h(unsigned u) {
    __half2 h; *reinterpret_cast<unsigned*>(&h) = u; return h;
}
__device__ __forceinline__ unsigned h2u(__half2 h) {
    return *reinterpret_cast<unsigned*>(&h);
}

// ---------------- f32x2 packed math (sm_100+) ----------------
__device__ __forceinline__ unsigned long long pk2(float a, float b) {
    unsigned long long r;
    asm("mov.b64 %0, {%1, %2};" : "=l"(r) : "r"(__float_as_uint(a)), "r"(__float_as_uint(b)));
    return r;
}
__device__ __forceinline__ float2 upk2(unsigned long long v) {
    unsigned lo, hi;
    asm("mov.b64 {%0, %1}, %2;" : "=r"(lo), "=r"(hi) : "l"(v));
    return make_float2(__uint_as_float(lo), __uint_as_float(hi));
}
__device__ __forceinline__ unsigned long long fma2(unsigned long long a,
                                                   unsigned long long b,
                                                   unsigned long long c) {
    unsigned long long d;
    asm("fma.rn.f32x2 %0, %1, %2, %3;" : "=l"(d) : "l"(a), "l"(b), "l"(c));
    return d;
}

// ---------------- helpers ----------------
__device__ __forceinline__ float gelu_t(float x) {
    // exact tanhf — used in the iterated/output path only
    float inner = 0.7978845608028654f * (x + 0.044715f * x * x * x);
    return 0.5f * x * (1.0f + tanhf(inner));
}
__device__ __forceinline__ float gelu_a(float x) {
    // tanh.approx.f32 — setup MLPs only (error ~2^-11, below fp16 storage rounding)
    float inner = 0.7978845608028654f * (x + 0.044715f * x * x * x);
    float t;
    asm("tanh.approx.f32 %0, %1;" : "=f"(t) : "f"(inner));
    return 0.5f * x * (1.0f + t);
}

// MLP weights packed: w1[32]@0, b1[16]@32, w2[256]@48, b2[16]@304, w3[1024]@320, b3[64]@1344
__device__ __forceinline__ void load_mlp_w(float* dst,
    const float* w1, const float* b1, const float* w2, const float* b2,
    const float* w3, const float* b3, int tid, int nthr) {
    for (int i = tid; i < 32;   i += nthr) dst[i]        = w1[i];
    for (int i = tid; i < 16;   i += nthr) dst[32 + i]   = b1[i];
    for (int i = tid; i < 256;  i += nthr) dst[48 + i]   = w2[i];
    for (int i = tid; i < 16;   i += nthr) dst[304 + i]  = b2[i];
    for (int i = tid; i < 1024; i += nthr) dst[320 + i]  = w3[i];
    for (int i = tid; i < 64;   i += nthr) dst[1344 + i] = b3[i];
}

// 2-input MLP through the second gelu layer; f32x2 packed h2 layer + approx gelu.
// Outputs h2p[16]: each h2 value duplicated into a packed f32x2 multiplier.
__device__ __forceinline__ void mlp2_h2p(const float* __restrict__ Wm, float x0, float x1,
                                         unsigned long long* h2p) {
    unsigned long long h1p[16];
#pragma unroll
    for (int o = 0; o < 16; o++) {
        float h = gelu_a(fmaf(x0, Wm[o], fmaf(x1, Wm[16 + o], Wm[32 + o])));
        h1p[o] = pk2(h, h);
    }
#pragma unroll
    for (int o = 0; o < 16; o += 2) {
        const float2 bv = *reinterpret_cast<const float2*>(&Wm[304 + o]);
        unsigned long long acc = pk2(bv.x, bv.y);
#pragma unroll
        for (int i = 0; i < 16; i++) {
            float2 wv = *reinterpret_cast<const float2*>(&Wm[48 + i * 16 + o]);
            acc = fma2(h1p[i], pk2(wv.x, wv.y), acc);
        }
        float2 r = upk2(acc);
        float a0 = gelu_a(r.x), a1 = gelu_a(r.y);
        h2p[o]     = pk2(a0, a0);
        h2p[o + 1] = pk2(a1, a1);
    }
}

// In-smem Stockham radix-4 FFT, length 256, nf transforms at stride TS,
// all smem indices permuted by PSW (conflict-free). NT = threads cooperating.
// tw[t] = exp(-2*pi*i*t/256). sign=+1 forward, sign=-1 unnormalized inverse.
// Caller syncs before. Result ends in xr/xi (4 swaps).
template <int NT>
__device__ __forceinline__ void fft4_stages(float* xr, float* xi, float* yr, float* yi,
                                            const float2* __restrict__ tw,
                                            int nf, int tid, float sign) {
    float *ar = xr, *ai = xi, *br = yr, *bi = yi;
#pragma unroll
    for (int s = 0; s < 4; s++) {
        int m = 1 << (2 * s);            // 1,4,16,64
        for (int t0 = tid; t0 < nf * 64; t0 += NT) {
            int base = (t0 >> 6) * TS;
            int t = t0 & 63;
            int jm = t & ~(m - 1);
            int r  = t & (m - 1);
            float2 w1v = tw[jm];
            float2 w2v = tw[2 * jm];
            float w1r = w1v.x, w1i = sign * w1v.y;
            float w2r = w2v.x, w2i = sign * w2v.y;

            float Ar = ar[base + PSW(t)],       Ai = ai[base + PSW(t)];
            float Br = ar[base + PSW(t + 64)],  Bi = ai[base + PSW(t + 64)];
            float Cr = ar[base + PSW(t + 128)], Ci = ai[base + PSW(t + 128)];
            float Dr = ar[base + PSW(t + 192)], Di = ai[base + PSW(t + 192)];

            float s0r = Ar + Cr, s0i = Ai + Ci;
            float d0r = Ar - Cr, d0i = Ai - Ci;
            float s2r = Br + Dr, s2i = Bi + Di;
            float d1r = Br - Dr, d1i = Bi - Di;
            float s1r = w1r * d0r - w1i * d0i;
            float s1i = w1r * d0i + w1i * d0r;
            float er = sign * d1i, ei = -sign * d1r;
            float s3r = w1r * er - w1i * ei;
            float s3i = w1r * ei + w1i * er;

            float u0r = s0r - s2r, u0i = s0i - s2i;
            float u1r = s1r - s3r, u1i = s1i - s3i;
            float o2r = w2r * u0r - w2i * u0i;
            float o2i = w2r * u0i + w2i * u0r;
            float o3r = w2r * u1r - w2i * u1i;
            float o3i = w2r * u1i + w2i * u1r;

            if (s == 0) {
                // m=1: contiguous outputs -> one float4 store per array
                int o = base + PSW(4 * t);
                *reinterpret_cast<float4*>(br + o) =
                    make_float4(s0r + s2r, s1r + s3r, o2r, o3r);
                *reinterpret_cast<float4*>(bi + o) =
                    make_float4(s0i + s2i, s1i + s3i, o2i, o3i);
            } else {
                int o = 4 * jm + r;
                br[base + PSW(o)]         = s0r + s2r;
                bi[base + PSW(o)]         = s0i + s2i;
                br[base + PSW(o + m)]     = s1r + s3r;
                bi[base + PSW(o + m)]     = s1i + s3i;
                br[base + PSW(o + 2 * m)] = o2r;
                bi[base + PSW(o + 2 * m)] = o2i;
                br[base + PSW(o + 3 * m)] = o3r;
                bi[base + PSW(o + 3 * m)] = o3i;
            }
        }
        __syncthreads();
        float* tp;
        tp = ar; ar = br; br = tp;
        tp = ai; ai = bi; bi = tp;
    }
}

__device__ __forceinline__ void fill_tw(float2* tws, int tid, int nthr) {
    for (int t = tid; t < 128; t += nthr) {
        float s, c;
        sincospif((float)t * (1.0f / 128.0f), &s, &c);
        tws[t] = make_float2(c, -s);
    }
}

// ---- shared tail: pack du, forward rfft_W, write Uf (used by k_gdf and k_row) ----
__device__ __forceinline__ void fwd_rfft_store(float* xr, float* xi, float* yr, float* yi,
                                               const float2* tws, const float* du,
                                               float2* ufrow, int tid) {
    int pw = PSW(tid);
#pragma unroll
    for (int p = 0; p < 4; p++) {
        xr[p * TS + pw] = du[2 * p];
        xi[p * TS + pw] = du[2 * p + 1];
    }
    __syncthreads();
    fft4_stages<256>(xr, xi, yr, yi, tws, 4, tid, 1.0f);    // forward
    if (tid <= 128) {
        int k2 = tid, m2 = (256 - k2) & 255;
        int pk2i = PSW(k2), pm2 = PSW(m2);
#pragma unroll
        for (int p = 0; p < 4; p++) {
            float Zr = xr[p * TS + pk2i], Zi = xi[p * TS + pk2i];
            float Qr = xr[p * TS + pm2], Qi = xi[p * TS + pm2];
            float2 A = make_float2(0.5f * (Zr + Qr), 0.5f * (Zi - Qi));
            float2 B = make_float2(0.5f * (Zi + Qi), 0.5f * (Qr - Zr));
            ufrow[k2 * 8 + 2 * p]     = A;
            ufrow[k2 * 8 + 2 * p + 1] = B;
        }
    }
}

// ---------------- kernel A (fused): G/D MLPs + iteration-0 du + rfft_W -> Uf --------
// Thread w owns pixel (row, w): it computes the full fp32 D matrix for that pixel,
// so du = u @ D is formed in-register from fp32 values (no fp16 roundtrip, no
// re-read of dmat). This replaces the former k_row<0> launch entirely.
__global__ __launch_bounds__(256) void k_gdf(const float* __restrict__ kin,
    const float* __restrict__ uin,
    const float* gw1, const float* gb1, const float* gw2, const float* gb2,
    const float* gw3, const float* gb3,
    const float* dw1, const float* db1, const float* dw2, const float* db2,
    const float* dw3, const float* db3) {
    __shared__ float Wg[1408], Wd[1408];
    __shared__ __align__(16) float xr[4 * TS], xi[4 * TS], yr[4 * TS], yi[4 * TS];
    __shared__ float2 tws[128];
    int tid = threadIdx.x;
    load_mlp_w(Wg, gw1, gb1, gw2, gb2, gw3, gb3, tid, 256);
    load_mlp_w(Wd, dw1, db1, dw2, db2, dw3, db3, tid, 256);
    fill_tw(tws, tid, 256);
    __syncthreads();

    int row = blockIdx.x;       // n*256 + h
    int w   = tid;
    int pix = row * 256 + w;
    float x0 = kin[pix * 2 + 0];
    float x1 = kin[pix * 2 + 1];

    float uu[8];
    {
        const float4* up = (const float4*)(uin + (size_t)row * 2048 + w * 8);
        float4 a = up[0], b = up[1];
        uu[0] = a.x; uu[1] = a.y; uu[2] = a.z; uu[3] = a.w;
        uu[4] = b.x; uu[5] = b.y; uu[6] = b.z; uu[7] = b.w;
    }

    unsigned long long h2p[16];
    const float inv64 = 1.0f / 64.0f;
    float du[8];
#pragma unroll
    for (int kk = 0; kk < 8; kk++) du[kk] = 0.0f;

    // delta MLP: store fp16 D, accumulate fp32 du = u @ D
    mlp2_h2p(Wd, x0, x1, h2p);
#pragma unroll
    for (int j = 0; j < 8; j++) {
        uint4 pk;
        unsigned* pku = &pk.x;
        float uj = uu[j];
#pragma unroll
        for (int p = 0; p < 4; p++) {
            int jk0 = j * 8 + 2 * p;
            const float2 bv = *reinterpret_cast<const float2*>(&Wd[1344 + jk0]);
            unsigned long long acc = pk2(bv.x, bv.y);
#pragma unroll
            for (int i = 0; i < 16; i++) {
                float2 wv = *reinterpret_cast<const float2*>(&Wd[320 + i * 64 + jk0]);
                acc = fma2(h2p[i], pk2(wv.x, wv.y), acc);
            }
            float2 r = upk2(acc);
            float v0 = r.x * inv64, v1 = r.y * inv64;
            du[2 * p]     = fmaf(uj, v0, du[2 * p]);
            du[2 * p + 1] = fmaf(uj, v1, du[2 * p + 1]);
            pku[p] = h2u(__floats2half2_rn(v0, v1));
        }
        *reinterpret_cast<uint4*>(d_dmat + ((size_t)(row * 8 + j) * 256 + w) * 4) = pk;
    }
    // gamma MLP: store fp16 G
    mlp2_h2p(Wg, x0, x1, h2p);
#pragma unroll
    for (int j = 0; j < 8; j++) {
        uint4 pk;
        unsigned* pku = &pk.x;
#pragma unroll
        for (int p = 0; p < 4; p++) {
            int jk0 = j * 8 + 2 * p;
            const float2 bv = *reinterpret_cast<const float2*>(&Wg[1344 + jk0]);
            unsigned long long acc = pk2(bv.x, bv.y);
#pragma unroll
            for (int i = 0; i < 16; i++) {
                float2 wv = *reinterpret_cast<const float2*>(&Wg[320 + i * 64 + jk0]);
                acc = fma2(h2p[i], pk2(wv.x, wv.y), acc);
            }
            float2 r = upk2(acc);
            pku[p] = h2u(__floats2half2_rn(r.x * inv64, r.y * inv64));
        }
        *reinterpret_cast<uint4*>(d_gmat + ((size_t)(row * 8 + j) * 256 + w) * 4) = pk;
    }

    // forward rfft_W of du -> Uf (iteration 0 row pass)
    float2* ufrow = d_uf + (size_t)row * 129 * 8;
    fwd_rfft_store(xr, xi, yr, yi, tws, du, ufrow, tid);
}

// ---------------- kernel B: spectral filter (fp16, [wf][g][j][hf][q], f32x2 MLP) ----
// MLP input (kx, ky) = (wf, signed(hf)). Scale = 1/64 only; the 1/65536 FFT
// normalization is applied in k_col's store (fp16 would underflow).
__global__ __launch_bounds__(256) void k_filt(
    const float* rw1, const float* rb1, const float* rw2, const float* rb2,
    const float* rw3, const float* rb3,
    const float* iw1, const float* ib1, const float* iw2, const float* ib2,
    const float* iw3, const float* ib3) {
    __shared__ float Wr[1408], Wi[1408];
    int tid = threadIdx.x;
    load_mlp_w(Wr, rw1, rb1, rw2, rb2, rw3, rb3, tid, 256);
    load_mlp_w(Wi, iw1, ib1, iw2, ib2, iw3, ib3, tid, 256);
    __syncthreads();

    int wf = blockIdx.x;
    int hf = tid;
    float x0 = (float)wf;
    float x1 = (float)(hf < 128 ? hf : hf - 256);
    unsigned long long h2rp[16], h2ip[16];
    mlp2_h2p(Wr, x0, x1, h2rp);
    mlp2_h2p(Wi, x0, x1, h2ip);
    const float sc = 1.0f / 64.0f;
#pragma unroll
    for (int g = 0; g < 2; g++) {
#pragma unroll
        for (int j = 0; j < 8; j++) {
            uint4 pk;
            unsigned* pku = &pk.x;
#pragma unroll
            for (int qq = 0; qq < 2; qq++) {           // pairs (q=2qq, 2qq+1)
                int jk0 = j * 8 + 4 * g + 2 * qq;
                const float2 bvr = *reinterpret_cast<const float2*>(&Wr[1344 + jk0]);
                const float2 bvi = *reinterpret_cast<const float2*>(&Wi[1344 + jk0]);
                unsigned long long accr = pk2(bvr.x, bvr.y);
                unsigned long long acci = pk2(bvi.x, bvi.y);
#pragma unroll
                for (int i = 0; i < 16; i++) {
                    float2 wvr = *reinterpret_cast<const float2*>(&Wr[320 + i * 64 + jk0]);
                    float2 wvi = *reinterpret_cast<const float2*>(&Wi[320 + i * 64 + jk0]);
                    accr = fma2(h2rp[i], pk2(wvr.x, wvr.y), accr);
                    acci = fma2(h2ip[i], pk2(wvi.x, wvi.y), acci);
                }
                float2 rr = upk2(accr);
                float2 ri = upk2(acci);
                pku[2 * qq]     = h2u(__floats2half2_rn(rr.x * sc, ri.x * sc));
                pku[2 * qq + 1] = h2u(__floats2half2_rn(rr.y * sc, ri.y * sc));
            }
            size_t idx = ((((size_t)wf * 2 + g) * 8 + j) * 256 + hf) * 4;
            *reinterpret_cast<uint4*>(d_filt + idx) = pk;
        }
    }
}

// ---------------- row pass (iterations 1..) ----------------
// MODE 1: gu = irfft_W(Uf) ; u' = 2u + (gu-u)@G -> d_u ; du = u'@D ; rfft_W -> Uf
// MODE 2: gu = irfft_W(Uf) ; u' = 2u + (gu-u)@G ; out = gelu(u'+bias)
// (256,4) bound is load-bearing: R8/R9 measured regs=64 @ 24.9us; without it
// ptxas went to 80 regs / occ 31% / 28.7us (R12).
template <int MODE>
__global__ __launch_bounds__(256, 4) void k_row(const float* __restrict__ uin,
                                                const float* __restrict__ bias,
                                                float* __restrict__ outp) {
    __shared__ __align__(16) float xr[4 * TS], xi[4 * TS], yr[4 * TS], yi[4 * TS];
    __shared__ float2 tws[128];

    int tid = threadIdx.x;
    int row = blockIdx.x;                       // n*256 + h
    fill_tw(tws, tid, 256);

    float2* ufrow = d_uf + (size_t)row * 129 * 8;
    const float* ubase = (uin != nullptr) ? uin : d_u;
    const float* urow  = ubase + (size_t)row * 2048;

    float unew[8];
    int w = tid;

    {
        // coalesced load of this thread's spectrum column (64B);
        // drop Im at DC/Nyquist (c2r semantics); Hermitian pack into xr/xi.
        int wfL = (tid <= 128) ? tid : 256 - tid;
        const float4* up = (const float4*)(ufrow + wfL * 8);
        float4 q0 = up[0], q1 = up[1], q2 = up[2], q3 = up[3];
        if (wfL == 0 || wfL == 128) {
            q0.y = 0.0f; q0.w = 0.0f; q1.y = 0.0f; q1.w = 0.0f;
            q2.y = 0.0f; q2.w = 0.0f; q3.y = 0.0f; q3.w = 0.0f;
        }
        float4 qs[4] = {q0, q1, q2, q3};
        int pt = PSW(tid);
        if (tid <= 128) {
#pragma unroll
            for (int p = 0; p < 4; p++) {
                xr[p * TS + pt] = qs[p].x - qs[p].w;   // A.x - B.y
                xi[p * TS + pt] = qs[p].y + qs[p].z;   // A.y + B.x
            }
        } else {
#pragma unroll
            for (int p = 0; p < 4; p++) {
                xr[p * TS + pt] = qs[p].x + qs[p].w;   // A.x + B.y
                xi[p * TS + pt] = qs[p].z - qs[p].y;   // B.x - A.y
            }
        }
        __syncthreads();
        fft4_stages<256>(xr, xi, yr, yi, tws, 4, tid, -1.0f);   // inverse (unnormalized)

        float gu[8], uu[8];
        int pw = PSW(w);
#pragma unroll
        for (int p = 0; p < 4; p++) {
            gu[2 * p]     = xr[p * TS + pw];
            gu[2 * p + 1] = xi[p * TS + pw];
        }
        {
            const float4* upu = (const float4*)(urow + w * 8);
            float4 a = upu[0], b = upu[1];
            uu[0] = a.x; uu[1] = a.y; uu[2] = a.z; uu[3] = a.w;
            uu[4] = b.x; uu[5] = b.y; uu[6] = b.z; uu[7] = b.w;
        }
        float tv[8];
#pragma unroll
        for (int j = 0; j < 8; j++) tv[j] = gu[j] - uu[j];
#pragma unroll
        for (int kk = 0; kk < 8; kk++) unew[kk] = 2.0f * uu[kk];
        const __half2* G = d_gmat + (size_t)row * 8 * 1024 + w * 4;
#pragma unroll
        for (int j = 0; j < 8; j++) {
            float tj = tv[j];
            uint4 raw = *reinterpret_cast<const uint4*>(G + j * 1024);
            float2 g0 = __half22float2(u2h(raw.x));
            float2 g1 = __half22float2(u2h(raw.y));
            float2 g2 = __half22float2(u2h(raw.z));
            float2 g3 = __half22float2(u2h(raw.w));
            unew[0] = fmaf(tj, g0.x, unew[0]); unew[1] = fmaf(tj, g0.y, unew[1]);
            unew[2] = fmaf(tj, g1.x, unew[2]); unew[3] = fmaf(tj, g1.y, unew[3]);
            unew[4] = fmaf(tj, g2.x, unew[4]); unew[5] = fmaf(tj, g2.y, unew[5]);
            unew[6] = fmaf(tj, g3.x, unew[6]); unew[7] = fmaf(tj, g3.y, unew[7]);
        }
        if (MODE == 2) {
            float4 o0, o1;
            o0.x = gelu_t(unew[0] + bias[0]);
            o0.y = gelu_t(unew[1] + bias[1]);
            o0.z = gelu_t(unew[2] + bias[2]);
            o0.w = gelu_t(unew[3] + bias[3]);
            o1.x = gelu_t(unew[4] + bias[4]);
            o1.y = gelu_t(unew[5] + bias[5]);
            o1.z = gelu_t(unew[6] + bias[6]);
            o1.w = gelu_t(unew[7] + bias[7]);
            float4* op = (float4*)(outp + (size_t)row * 2048 + w * 8);
            op[0] = o0; op[1] = o1;
            return;
        }
        // MODE 1: persist u'
        {
            float4 o0, o1;
            o0.x = unew[0]; o0.y = unew[1]; o0.z = unew[2]; o0.w = unew[3];
            o1.x = unew[4]; o1.y = unew[5]; o1.z = unew[6]; o1.w = unew[7];
            float4* op = (float4*)(d_u + (size_t)row * 2048 + w * 8);
            op[0] = o0; op[1] = o1;
        }
    }

    // du = unew @ D ; pack ; forward FFT ; unpack rfft ; write Uf
    {
        const __half2* D = d_dmat + (size_t)row * 8 * 1024 + w * 4;
        float du[8];
#pragma unroll
        for (int kk = 0; kk < 8; kk++) du[kk] = 0.0f;
#pragma unroll
        for (int j = 0; j < 8; j++) {
            float uj = unew[j];
            uint4 raw = *reinterpret_cast<const uint4*>(D + j * 1024);
            float2 g0 = __half22float2(u2h(raw.x));
            float2 g1 = __half22float2(u2h(raw.y));
            float2 g2 = __half22float2(u2h(raw.z));
            float2 g3 = __half22float2(u2h(raw.w));
            du[0] = fmaf(uj, g0.x, du[0]); du[1] = fmaf(uj, g0.y, du[1]);
            du[2] = fmaf(uj, g1.x, du[2]); du[3] = fmaf(uj, g1.y, du[3]);
            du[4] = fmaf(uj, g2.x, du[4]); du[5] = fmaf(uj, g2.y, du[5]);
            du[6] = fmaf(uj, g3.x, du[6]); du[7] = fmaf(uj, g3.y, du[7]);
        }
        __syncthreads();   // all gu reads of xr/xi complete
        fwd_rfft_store(xr, xi, yr, yi, tws, du, ufrow, tid);
    }
}

// ---------------- column pass: FFT_H, filter matvec, IFFT_H (in-place on Uf) ---------
// 512 threads: one butterfly per thread per stage; matvec split by kk-half.
// R10 form (21.9us). No reg cap (R8: caps spill); 256-thr/2-butterfly was slower (R11).
__global__ __launch_bounds__(512) void k_col() {
    __shared__ __align__(16) float xr[8 * TS], xi[8 * TS], yr[8 * TS], yi[8 * TS];
    __shared__ float2 tws[128];
    int tid = threadIdx.x;
    int wf = blockIdx.x % 129;
    int n  = blockIdx.x / 129;
    fill_tw(tws, tid, 512);

    float2* base = d_uf + ((size_t)n * 256 * 129 + wf) * 8;  // + h*129*8 + c
    for (int it = 0; it < 4; it++) {
        int idx = it * 512 + tid;
        int h = idx >> 3, c = idx & 7;
        float2 v = base[(size_t)h * 129 * 8 + c];
        int a = c * TS + PSW(h);
        xr[a] = v.x;
        xi[a] = v.y;
    }
    __syncthreads();
    fft4_stages<512>(xr, xi, yr, yi, tws, 8, tid, 1.0f);     // forward along H

    int hf = tid & 255;
    int g  = tid >> 8;          // kk-half
    int ph = PSW(hf);
    float vr[4], vi[4];
#pragma unroll
    for (int q = 0; q < 4; q++) { vr[q] = 0.0f; vi[q] = 0.0f; }
    const __half2* F = d_filt + (((size_t)wf * 2 + g) * 8 * 256 + hf) * 4;
#pragma unroll
    for (int j = 0; j < 8; j++) {
        float zr = xr[j * TS + ph], zi = xi[j * TS + ph];
        uint4 fa = *reinterpret_cast<const uint4*>(F + (size_t)j * 1024);
        const unsigned* fu = &fa.x;
#pragma unroll
        for (int q = 0; q < 4; q++) {
            float2 f = __half22float2(u2h(fu[q]));
            vr[q] = fmaf(zr, f.x, fmaf(-zi, f.y, vr[q]));
            vi[q] = fmaf(zr, f.y, fmaf(zi, f.x, vi[q]));
        }
    }
    __syncthreads();
#pragma unroll
    for (int q = 0; q < 4; q++) {
        int kk = 4 * g + q;
        yr[kk * TS + ph] = vr[q];
        yi[kk * TS + ph] = vi[q];
    }
    __syncthreads();
    fft4_stages<512>(yr, yi, xr, xi, tws, 8, tid, -1.0f);    // inverse (unnormalized)

    const float inv = 1.0f / 65536.0f;  // both inverse-FFT norms (kept out of fp16 filt)
    for (int it = 0; it < 4; it++) {
        int idx = it * 512 + tid;
        int h = idx >> 3, c = idx & 7;
        int a = c * TS + PSW(h);
        base[(size_t)h * 129 * 8 + c] = make_float2(yr[a] * inv, yi[a] * inv);
    }
}

// ---------------- launch ----------------
extern "C" void kernel_launch(void* const* d_in, const int* in_sizes, int n_in,
                              void* d_out, int out_size) {
    const float* u    = (const float*)d_in[0];
    const float* kk   = (const float*)d_in[1];
    const float* gW[6];  for (int i = 0; i < 6; i++) gW[i]  = (const float*)d_in[2 + i];
    const float* dW[6];  for (int i = 0; i < 6; i++) dW[i]  = (const float*)d_in[8 + i];
    const float* frW[6]; for (int i = 0; i < 6; i++) frW[i] = (const float*)d_in[14 + i];
    const float* fiW[6]; for (int i = 0; i < 6; i++) fiW[i] = (const float*)d_in[20 + i];
    const float* bias = (const float*)d_in[26];
    float* out = (float*)d_out;

    // fused: G/D MLPs + iteration-0 row pass (du + rfft_W -> Uf)
    k_gdf<<<NROW, 256>>>(kk, u,
        gW[0], gW[1], gW[2], gW[3], gW[4], gW[5],
        dW[0], dW[1], dW[2], dW[3], dW[4], dW[5]);
    k_filt<<<129, 256>>>(
        frW[0], frW[1], frW[2], frW[3], frW[4], frW[5],
        fiW[0], fiW[1], fiW[2], fiW[3], fiW[4], fiW[5]);

    for (int it = 0; it < 4; it++) {
        k_col<<<4 * 129, 512>>>();
        if (it < 3) {
            k_row<1><<<NROW, 256>>>(it == 0 ? u : nullptr, nullptr, nullptr);
        } else {
            k_row<2><<<NROW, 256>>>(nullptr, bias, out);
        }
    }
}

// round 14
// speedup vs baseline: 1.0693x; 1.0412x over previous
#include <cuda_runtime.h>
#include <cuda_fp16.h>
#include <cstddef>
#include <math.h>

// Problem constants: N=4, H=W=256, C=8, CK=2, ITER=4, HID=16, C2=64.
#define NROW 1024            // n*256+h rows
#define TS 260               // per-transform smem stride (floats)

// Bank-conflict-free smem permutation for the radix-4 Stockham access sets.
// P(i) = i ^ ((i>>2)&28): invertible, preserves aligned 4-blocks.
__device__ __forceinline__ int PSW(int i) { return i ^ ((i >> 2) & 28); }

// ---------------- device scratch (no allocations allowed) ----------------
// gmat/dmat: [row][j][w][p]  p=half2 pair over k  (1024*8*256*4 half2 = 33.5MB each)
__device__ __align__(16) __half2 d_gmat[8388608];
__device__ __align__(16) __half2 d_dmat[8388608];
// filt: [wf][g][j][hf][q]  g=kk-half, q=0..3 -> kk=4g+q   (129*2*8*256*4 half2 = 8.45MB)
__device__ __align__(16) __half2 d_filt[(size_t)129 * 2 * 8 * 256 * 4];
__device__ __align__(16) float2 d_uf[(size_t)1024 * 129 * 8]; // [row][wf][c]
__device__ __align__(16) float  d_u[(size_t)1024 * 256 * 8];  // iterated field

__device__ __forceinline__ __half2 u2h(unsigned u) {
    __half2 h; *reinterpret_cast<unsigned*>(&h) = u; return h;
}
__device__ __forceinline__ unsigned h2u(__half2 h) {
    return *reinterpret_cast<unsigned*>(&h);
}

// ---------------- f32x2 packed math (sm_100+) ----------------
__device__ __forceinline__ unsigned long long pk2(float a, float b) {
    unsigned long long r;
    asm("mov.b64 %0, {%1, %2};" : "=l"(r) : "r"(__float_as_uint(a)), "r"(__float_as_uint(b)));
    return r;
}
__device__ __forceinline__ float2 upk2(unsigned long long v) {
    unsigned lo, hi;
    asm("mov.b64 {%0, %1}, %2;" : "=r"(lo), "=r"(hi) : "l"(v));
    return make_float2(__uint_as_float(lo), __uint_as_float(hi));
}
__device__ __forceinline__ unsigned long long fma2(unsigned long long a,
                                                   unsigned long long b,
                                                   unsigned long long c) {
    unsigned long long d;
    asm("fma.rn.f32x2 %0, %1, %2, %3;" : "=l"(d) : "l"(a), "l"(b), "l"(c));
    return d;
}

// ---------------- helpers ----------------
__device__ __forceinline__ float gelu_t(float x) {
    // exact tanhf — used in the iterated/output path only
    float inner = 0.7978845608028654f * (x + 0.044715f * x * x * x);
    return 0.5f * x * (1.0f + tanhf(inner));
}
__device__ __forceinline__ float gelu_a(float x) {
    // tanh.approx.f32 — setup MLPs only (error ~2^-11, below fp16 storage rounding)
    float inner = 0.7978845608028654f * (x + 0.044715f * x * x * x);
    float t;
    asm("tanh.approx.f32 %0, %1;" : "=f"(t) : "f"(inner));
    return 0.5f * x * (1.0f + t);
}

// MLP weights packed: w1[32]@0, b1[16]@32, w2[256]@48, b2[16]@304, w3[1024]@320, b3[64]@1344
__device__ __forceinline__ void load_mlp_w(float* dst,
    const float* w1, const float* b1, const float* w2, const float* b2,
    const float* w3, const float* b3, int tid, int nthr) {
    for (int i = tid; i < 32;   i += nthr) dst[i]        = w1[i];
    for (int i = tid; i < 16;   i += nthr) dst[32 + i]   = b1[i];
    for (int i = tid; i < 256;  i += nthr) dst[48 + i]   = w2[i];
    for (int i = tid; i < 16;   i += nthr) dst[304 + i]  = b2[i];
    for (int i = tid; i < 1024; i += nthr) dst[320 + i]  = w3[i];
    for (int i = tid; i < 64;   i += nthr) dst[1344 + i] = b3[i];
}

// 2-input MLP through the second gelu layer; f32x2 packed h2 layer + approx gelu.
// Outputs h2p[16]: each h2 value duplicated into a packed f32x2 multiplier.
__device__ __forceinline__ void mlp2_h2p(const float* __restrict__ Wm, float x0, float x1,
                                         unsigned long long* h2p) {
    unsigned long long h1p[16];
#pragma unroll
    for (int o = 0; o < 16; o++) {
        float h = gelu_a(fmaf(x0, Wm[o], fmaf(x1, Wm[16 + o], Wm[32 + o])));
        h1p[o] = pk2(h, h);
    }
#pragma unroll
    for (int o = 0; o < 16; o += 2) {
        const float2 bv = *reinterpret_cast<const float2*>(&Wm[304 + o]);
        unsigned long long acc = pk2(bv.x, bv.y);
#pragma unroll
        for (int i = 0; i < 16; i++) {
            float2 wv = *reinterpret_cast<const float2*>(&Wm[48 + i * 16 + o]);
            acc = fma2(h1p[i], pk2(wv.x, wv.y), acc);
        }
        float2 r = upk2(acc);
        float a0 = gelu_a(r.x), a1 = gelu_a(r.y);
        h2p[o]     = pk2(a0, a0);
        h2p[o + 1] = pk2(a1, a1);
    }
}

// In-smem Stockham radix-4 FFT, length 256, nf transforms at stride TS,
// all smem indices permuted by PSW (conflict-free). NT = threads cooperating.
// tw[t] = exp(-2*pi*i*t/256). sign=+1 forward, sign=-1 unnormalized inverse.
// Caller syncs before. Result ends in xr/xi (4 swaps).
template <int NT>
__device__ __forceinline__ void fft4_stages(float* xr, float* xi, float* yr, float* yi,
                                            const float2* __restrict__ tw,
                                            int nf, int tid, float sign) {
    float *ar = xr, *ai = xi, *br = yr, *bi = yi;
#pragma unroll
    for (int s = 0; s < 4; s++) {
        int m = 1 << (2 * s);            // 1,4,16,64
        for (int t0 = tid; t0 < nf * 64; t0 += NT) {
            int base = (t0 >> 6) * TS;
            int t = t0 & 63;
            int jm = t & ~(m - 1);
            int r  = t & (m - 1);
            float2 w1v = tw[jm];
            float2 w2v = tw[2 * jm];
            float w1r = w1v.x, w1i = sign * w1v.y;
            float w2r = w2v.x, w2i = sign * w2v.y;

            float Ar = ar[base + PSW(t)],       Ai = ai[base + PSW(t)];
            float Br = ar[base + PSW(t + 64)],  Bi = ai[base + PSW(t + 64)];
            float Cr = ar[base + PSW(t + 128)], Ci = ai[base + PSW(t + 128)];
            float Dr = ar[base + PSW(t + 192)], Di = ai[base + PSW(t + 192)];

            float s0r = Ar + Cr, s0i = Ai + Ci;
            float d0r = Ar - Cr, d0i = Ai - Ci;
            float s2r = Br + Dr, s2i = Bi + Di;
            float d1r = Br - Dr, d1i = Bi - Di;
            float s1r = w1r * d0r - w1i * d0i;
            float s1i = w1r * d0i + w1i * d0r;
            float er = sign * d1i, ei = -sign * d1r;
            float s3r = w1r * er - w1i * ei;
            float s3i = w1r * ei + w1i * er;

            float u0r = s0r - s2r, u0i = s0i - s2i;
            float u1r = s1r - s3r, u1i = s1i - s3i;
            float o2r = w2r * u0r - w2i * u0i;
            float o2i = w2r * u0i + w2i * u0r;
            float o3r = w2r * u1r - w2i * u1i;
            float o3i = w2r * u1i + w2i * u1r;

            if (s == 0) {
                // m=1: contiguous outputs -> one float4 store per array
                int o = base + PSW(4 * t);
                *reinterpret_cast<float4*>(br + o) =
                    make_float4(s0r + s2r, s1r + s3r, o2r, o3r);
                *reinterpret_cast<float4*>(bi + o) =
                    make_float4(s0i + s2i, s1i + s3i, o2i, o3i);
            } else {
                int o = 4 * jm + r;
                br[base + PSW(o)]         = s0r + s2r;
                bi[base + PSW(o)]         = s0i + s2i;
                br[base + PSW(o + m)]     = s1r + s3r;
                bi[base + PSW(o + m)]     = s1i + s3i;
                br[base + PSW(o + 2 * m)] = o2r;
                bi[base + PSW(o + 2 * m)] = o2i;
                br[base + PSW(o + 3 * m)] = o3r;
                bi[base + PSW(o + 3 * m)] = o3i;
            }
        }
        __syncthreads();
        float* tp;
        tp = ar; ar = br; br = tp;
        tp = ai; ai = bi; bi = tp;
    }
}

__device__ __forceinline__ void fill_tw(float2* tws, int tid, int nthr) {
    for (int t = tid; t < 128; t += nthr) {
        float s, c;
        sincospif((float)t * (1.0f / 128.0f), &s, &c);
        tws[t] = make_float2(c, -s);
    }
}

// ---- shared tail: pack du, forward rfft_W, write Uf (used by k_gdf and k_row) ----
__device__ __forceinline__ void fwd_rfft_store(float* xr, float* xi, float* yr, float* yi,
                                               const float2* tws, const float* du,
                                               float2* ufrow, int tid) {
    int pw = PSW(tid);
#pragma unroll
    for (int p = 0; p < 4; p++) {
        xr[p * TS + pw] = du[2 * p];
        xi[p * TS + pw] = du[2 * p + 1];
    }
    __syncthreads();
    fft4_stages<256>(xr, xi, yr, yi, tws, 4, tid, 1.0f);    // forward
    if (tid <= 128) {
        int k2 = tid, m2 = (256 - k2) & 255;
        int pk2i = PSW(k2), pm2 = PSW(m2);
#pragma unroll
        for (int p = 0; p < 4; p++) {
            float Zr = xr[p * TS + pk2i], Zi = xi[p * TS + pk2i];
            float Qr = xr[p * TS + pm2], Qi = xi[p * TS + pm2];
            float2 A = make_float2(0.5f * (Zr + Qr), 0.5f * (Zi - Qi));
            float2 B = make_float2(0.5f * (Zi + Qi), 0.5f * (Qr - Zr));
            ufrow[k2 * 8 + 2 * p]     = A;
            ufrow[k2 * 8 + 2 * p + 1] = B;
        }
    }
}

// ---------------- kernel A (fused): G/D MLPs + iteration-0 du + rfft_W -> Uf --------
// Thread w owns pixel (row, w): it computes the full fp32 D matrix for that pixel,
// so du = u @ D is formed in-register from fp32 values (no fp16 roundtrip, no
// re-read of dmat). This replaces the former k_row<0> launch entirely.
__global__ __launch_bounds__(256) void k_gdf(const float* __restrict__ kin,
    const float* __restrict__ uin,
    const float* gw1, const float* gb1, const float* gw2, const float* gb2,
    const float* gw3, const float* gb3,
    const float* dw1, const float* db1, const float* dw2, const float* db2,
    const float* dw3, const float* db3) {
    __shared__ float Wg[1408], Wd[1408];
    __shared__ __align__(16) float xr[4 * TS], xi[4 * TS], yr[4 * TS], yi[4 * TS];
    __shared__ float2 tws[128];
    int tid = threadIdx.x;
    load_mlp_w(Wg, gw1, gb1, gw2, gb2, gw3, gb3, tid, 256);
    load_mlp_w(Wd, dw1, db1, dw2, db2, dw3, db3, tid, 256);
    fill_tw(tws, tid, 256);
    __syncthreads();

    int row = blockIdx.x;       // n*256 + h
    int w   = tid;
    int pix = row * 256 + w;
    float x0 = kin[pix * 2 + 0];
    float x1 = kin[pix * 2 + 1];

    float uu[8];
    {
        const float4* up = (const float4*)(uin + (size_t)row * 2048 + w * 8);
        float4 a = up[0], b = up[1];
        uu[0] = a.x; uu[1] = a.y; uu[2] = a.z; uu[3] = a.w;
        uu[4] = b.x; uu[5] = b.y; uu[6] = b.z; uu[7] = b.w;
    }

    unsigned long long h2p[16];
    const float inv64 = 1.0f / 64.0f;
    float du[8];
#pragma unroll
    for (int kk = 0; kk < 8; kk++) du[kk] = 0.0f;

    // delta MLP: store fp16 D, accumulate fp32 du = u @ D
    mlp2_h2p(Wd, x0, x1, h2p);
#pragma unroll
    for (int j = 0; j < 8; j++) {
        uint4 pk;
        unsigned* pku = &pk.x;
        float uj = uu[j];
#pragma unroll
        for (int p = 0; p < 4; p++) {
            int jk0 = j * 8 + 2 * p;
            const float2 bv = *reinterpret_cast<const float2*>(&Wd[1344 + jk0]);
            unsigned long long acc = pk2(bv.x, bv.y);
#pragma unroll
            for (int i = 0; i < 16; i++) {
                float2 wv = *reinterpret_cast<const float2*>(&Wd[320 + i * 64 + jk0]);
                acc = fma2(h2p[i], pk2(wv.x, wv.y), acc);
            }
            float2 r = upk2(acc);
            float v0 = r.x * inv64, v1 = r.y * inv64;
            du[2 * p]     = fmaf(uj, v0, du[2 * p]);
            du[2 * p + 1] = fmaf(uj, v1, du[2 * p + 1]);
            pku[p] = h2u(__floats2half2_rn(v0, v1));
        }
        *reinterpret_cast<uint4*>(d_dmat + ((size_t)(row * 8 + j) * 256 + w) * 4) = pk;
    }
    // gamma MLP: store fp16 G
    mlp2_h2p(Wg, x0, x1, h2p);
#pragma unroll
    for (int j = 0; j < 8; j++) {
        uint4 pk;
        unsigned* pku = &pk.x;
#pragma unroll
        for (int p = 0; p < 4; p++) {
            int jk0 = j * 8 + 2 * p;
            const float2 bv = *reinterpret_cast<const float2*>(&Wg[1344 + jk0]);
            unsigned long long acc = pk2(bv.x, bv.y);
#pragma unroll
            for (int i = 0; i < 16; i++) {
                float2 wv = *reinterpret_cast<const float2*>(&Wg[320 + i * 64 + jk0]);
                acc = fma2(h2p[i], pk2(wv.x, wv.y), acc);
            }
            float2 r = upk2(acc);
            pku[p] = h2u(__floats2half2_rn(r.x * inv64, r.y * inv64));
        }
        *reinterpret_cast<uint4*>(d_gmat + ((size_t)(row * 8 + j) * 256 + w) * 4) = pk;
    }

    // forward rfft_W of du -> Uf (iteration 0 row pass)
    float2* ufrow = d_uf + (size_t)row * 129 * 8;
    fwd_rfft_store(xr, xi, yr, yi, tws, du, ufrow, tid);
}

// ---------------- kernel B: spectral filter (fp16, [wf][g][j][hf][q], f32x2 MLP) ----
// MLP input (kx, ky) = (wf, signed(hf)). Scale = 1/64 only; the 1/65536 FFT
// normalization is applied in k_col's store (fp16 would underflow).
__global__ __launch_bounds__(256) void k_filt(
    const float* rw1, const float* rb1, const float* rw2, const float* rb2,
    const float* rw3, const float* rb3,
    const float* iw1, const float* ib1, const float* iw2, const float* ib2,
    const float* iw3, const float* ib3) {
    __shared__ float Wr[1408], Wi[1408];
    int tid = threadIdx.x;
    load_mlp_w(Wr, rw1, rb1, rw2, rb2, rw3, rb3, tid, 256);
    load_mlp_w(Wi, iw1, ib1, iw2, ib2, iw3, ib3, tid, 256);
    __syncthreads();

    int wf = blockIdx.x;
    int hf = tid;
    float x0 = (float)wf;
    float x1 = (float)(hf < 128 ? hf : hf - 256);
    unsigned long long h2rp[16], h2ip[16];
    mlp2_h2p(Wr, x0, x1, h2rp);
    mlp2_h2p(Wi, x0, x1, h2ip);
    const float sc = 1.0f / 64.0f;
#pragma unroll
    for (int g = 0; g < 2; g++) {
#pragma unroll
        for (int j = 0; j < 8; j++) {
            uint4 pk;
            unsigned* pku = &pk.x;
#pragma unroll
            for (int qq = 0; qq < 2; qq++) {           // pairs (q=2qq, 2qq+1)
                int jk0 = j * 8 + 4 * g + 2 * qq;
                const float2 bvr = *reinterpret_cast<const float2*>(&Wr[1344 + jk0]);
                const float2 bvi = *reinterpret_cast<const float2*>(&Wi[1344 + jk0]);
                unsigned long long accr = pk2(bvr.x, bvr.y);
                unsigned long long acci = pk2(bvi.x, bvi.y);
#pragma unroll
                for (int i = 0; i < 16; i++) {
                    float2 wvr = *reinterpret_cast<const float2*>(&Wr[320 + i * 64 + jk0]);
                    float2 wvi = *reinterpret_cast<const float2*>(&Wi[320 + i * 64 + jk0]);
                    accr = fma2(h2rp[i], pk2(wvr.x, wvr.y), accr);
                    acci = fma2(h2ip[i], pk2(wvi.x, wvi.y), acci);
                }
                float2 rr = upk2(accr);
                float2 ri = upk2(acci);
                pku[2 * qq]     = h2u(__floats2half2_rn(rr.x * sc, ri.x * sc));
                pku[2 * qq + 1] = h2u(__floats2half2_rn(rr.y * sc, ri.y * sc));
            }
            size_t idx = ((((size_t)wf * 2 + g) * 8 + j) * 256 + hf) * 4;
            *reinterpret_cast<uint4*>(d_filt + idx) = pk;
        }
    }
}

// ---------------- row pass (iterations 1..) ----------------
// MODE 1: gu = irfft_W(Uf) ; u' = 2u + (gu-u)@G -> d_u ; du = u'@D ; rfft_W -> Uf
// MODE 2: gu = irfft_W(Uf) ; u' = 2u + (gu-u)@G ; out = gelu(u'+bias)
// (256,4) bound is load-bearing: R8/R9/R13 measured regs=64 @ ~25us; without it
// ptxas went to 80 regs / occ 31% / 28.7us (R12).
template <int MODE>
__global__ __launch_bounds__(256, 4) void k_row(const float* __restrict__ uin,
                                                const float* __restrict__ bias,
                                                float* __restrict__ outp) {
    __shared__ __align__(16) float xr[4 * TS], xi[4 * TS], yr[4 * TS], yi[4 * TS];
    __shared__ float2 tws[128];

    int tid = threadIdx.x;
    int row = blockIdx.x;                       // n*256 + h
    fill_tw(tws, tid, 256);

    float2* ufrow = d_uf + (size_t)row * 129 * 8;
    const float* ubase = (uin != nullptr) ? uin : d_u;
    const float* urow  = ubase + (size_t)row * 2048;

    float unew[8];
    int w = tid;

    {
        // coalesced load of this thread's spectrum column (64B);
        // drop Im at DC/Nyquist (c2r semantics); Hermitian pack into xr/xi.
        int wfL = (tid <= 128) ? tid : 256 - tid;
        const float4* up = (const float4*)(ufrow + wfL * 8);
        float4 q0 = up[0], q1 = up[1], q2 = up[2], q3 = up[3];
        if (wfL == 0 || wfL == 128) {
            q0.y = 0.0f; q0.w = 0.0f; q1.y = 0.0f; q1.w = 0.0f;
            q2.y = 0.0f; q2.w = 0.0f; q3.y = 0.0f; q3.w = 0.0f;
        }
        float4 qs[4] = {q0, q1, q2, q3};
        int pt = PSW(tid);
        if (tid <= 128) {
#pragma unroll
            for (int p = 0; p < 4; p++) {
                xr[p * TS + pt] = qs[p].x - qs[p].w;   // A.x - B.y
                xi[p * TS + pt] = qs[p].y + qs[p].z;   // A.y + B.x
            }
        } else {
#pragma unroll
            for (int p = 0; p < 4; p++) {
                xr[p * TS + pt] = qs[p].x + qs[p].w;   // A.x + B.y
                xi[p * TS + pt] = qs[p].z - qs[p].y;   // B.x - A.y
            }
        }
        __syncthreads();
        fft4_stages<256>(xr, xi, yr, yi, tws, 4, tid, -1.0f);   // inverse (unnormalized)

        float gu[8], uu[8];
        int pw = PSW(w);
#pragma unroll
        for (int p = 0; p < 4; p++) {
            gu[2 * p]     = xr[p * TS + pw];
            gu[2 * p + 1] = xi[p * TS + pw];
        }
        {
            const float4* upu = (const float4*)(urow + w * 8);
            float4 a = upu[0], b = upu[1];
            uu[0] = a.x; uu[1] = a.y; uu[2] = a.z; uu[3] = a.w;
            uu[4] = b.x; uu[5] = b.y; uu[6] = b.z; uu[7] = b.w;
        }
        float tv[8];
#pragma unroll
        for (int j = 0; j < 8; j++) tv[j] = gu[j] - uu[j];
#pragma unroll
        for (int kk = 0; kk < 8; kk++) unew[kk] = 2.0f * uu[kk];
        const __half2* G = d_gmat + (size_t)row * 8 * 1024 + w * 4;
#pragma unroll
        for (int j = 0; j < 8; j++) {
            float tj = tv[j];
            uint4 raw = *reinterpret_cast<const uint4*>(G + j * 1024);
            float2 g0 = __half22float2(u2h(raw.x));
            float2 g1 = __half22float2(u2h(raw.y));
            float2 g2 = __half22float2(u2h(raw.z));
            float2 g3 = __half22float2(u2h(raw.w));
            unew[0] = fmaf(tj, g0.x, unew[0]); unew[1] = fmaf(tj, g0.y, unew[1]);
            unew[2] = fmaf(tj, g1.x, unew[2]); unew[3] = fmaf(tj, g1.y, unew[3]);
            unew[4] = fmaf(tj, g2.x, unew[4]); unew[5] = fmaf(tj, g2.y, unew[5]);
            unew[6] = fmaf(tj, g3.x, unew[6]); unew[7] = fmaf(tj, g3.y, unew[7]);
        }
        if (MODE == 2) {
            float4 o0, o1;
            o0.x = gelu_t(unew[0] + bias[0]);
            o0.y = gelu_t(unew[1] + bias[1]);
            o0.z = gelu_t(unew[2] + bias[2]);
            o0.w = gelu_t(unew[3] + bias[3]);
            o1.x = gelu_t(unew[4] + bias[4]);
            o1.y = gelu_t(unew[5] + bias[5]);
            o1.z = gelu_t(unew[6] + bias[6]);
            o1.w = gelu_t(unew[7] + bias[7]);
            float4* op = (float4*)(outp + (size_t)row * 2048 + w * 8);
            op[0] = o0; op[1] = o1;
            return;
        }
        // MODE 1: persist u'
        {
            float4 o0, o1;
            o0.x = unew[0]; o0.y = unew[1]; o0.z = unew[2]; o0.w = unew[3];
            o1.x = unew[4]; o1.y = unew[5]; o1.z = unew[6]; o1.w = unew[7];
            float4* op = (float4*)(d_u + (size_t)row * 2048 + w * 8);
            op[0] = o0; op[1] = o1;
        }
    }

    // du = unew @ D ; pack ; forward FFT ; unpack rfft ; write Uf
    {
        const __half2* D = d_dmat + (size_t)row * 8 * 1024 + w * 4;
        float du[8];
#pragma unroll
        for (int kk = 0; kk < 8; kk++) du[kk] = 0.0f;
#pragma unroll
        for (int j = 0; j < 8; j++) {
            float uj = unew[j];
            uint4 raw = *reinterpret_cast<const uint4*>(D + j * 1024);
            float2 g0 = __half22float2(u2h(raw.x));
            float2 g1 = __half22float2(u2h(raw.y));
            float2 g2 = __half22float2(u2h(raw.z));
            float2 g3 = __half22float2(u2h(raw.w));
            du[0] = fmaf(uj, g0.x, du[0]); du[1] = fmaf(uj, g0.y, du[1]);
            du[2] = fmaf(uj, g1.x, du[2]); du[3] = fmaf(uj, g1.y, du[3]);
            du[4] = fmaf(uj, g2.x, du[4]); du[5] = fmaf(uj, g2.y, du[5]);
            du[6] = fmaf(uj, g3.x, du[6]); du[7] = fmaf(uj, g3.y, du[7]);
        }
        __syncthreads();   // all gu reads of xr/xi complete
        fwd_rfft_store(xr, xi, yr, yi, tws, du, ufrow, tid);
    }
}

// ---------------- column pass: FFT_H, filter matvec, IFFT_H (in-place on Uf) ---------
// 512 threads: one butterfly per thread per stage; matvec split by kk-half.
// (512,2): forces ~64 regs -> 2 blocks/SM (32 warps). R8's regression was
// confounded with a per-block n-loop; R8-vs-R9 differential shows cap+loop cost
// only +3.2us total, so the cap alone is worth retrying for the 2x residency.
__global__ __launch_bounds__(512, 2) void k_col() {
    __shared__ __align__(16) float xr[8 * TS], xi[8 * TS], yr[8 * TS], yi[8 * TS];
    __shared__ float2 tws[128];
    int tid = threadIdx.x;
    int wf = blockIdx.x % 129;
    int n  = blockIdx.x / 129;
    fill_tw(tws, tid, 512);

    float2* base = d_uf + ((size_t)n * 256 * 129 + wf) * 8;  // + h*129*8 + c
    for (int it = 0; it < 4; it++) {
        int idx = it * 512 + tid;
        int h = idx >> 3, c = idx & 7;
        float2 v = base[(size_t)h * 129 * 8 + c];
        int a = c * TS + PSW(h);
        xr[a] = v.x;
        xi[a] = v.y;
    }
    __syncthreads();
    fft4_stages<512>(xr, xi, yr, yi, tws, 8, tid, 1.0f);     // forward along H

    int hf = tid & 255;
    int g  = tid >> 8;          // kk-half
    int ph = PSW(hf);
    float vr[4], vi[4];
#pragma unroll
    for (int q = 0; q < 4; q++) { vr[q] = 0.0f; vi[q] = 0.0f; }
    const __half2* F = d_filt + (((size_t)wf * 2 + g) * 8 * 256 + hf) * 4;
#pragma unroll
    for (int j = 0; j < 8; j++) {
        float zr = xr[j * TS + ph], zi = xi[j * TS + ph];
        uint4 fa = *reinterpret_cast<const uint4*>(F + (size_t)j * 1024);
        const unsigned* fu = &fa.x;
#pragma unroll
        for (int q = 0; q < 4; q++) {
            float2 f = __half22float2(u2h(fu[q]));
            vr[q] = fmaf(zr, f.x, fmaf(-zi, f.y, vr[q]));
            vi[q] = fmaf(zr, f.y, fmaf(zi, f.x, vi[q]));
        }
    }
    __syncthreads();
#pragma unroll
    for (int q = 0; q < 4; q++) {
        int kk = 4 * g + q;
        yr[kk * TS + ph] = vr[q];
        yi[kk * TS + ph] = vi[q];
    }
    __syncthreads();
    fft4_stages<512>(yr, yi, xr, xi, tws, 8, tid, -1.0f);    // inverse (unnormalized)

    const float inv = 1.0f / 65536.0f;  // both inverse-FFT norms (kept out of fp16 filt)
    for (int it = 0; it < 4; it++) {
        int idx = it * 512 + tid;
        int h = idx >> 3, c = idx & 7;
        int a = c * TS + PSW(h);
        base[(size_t)h * 129 * 8 + c] = make_float2(yr[a] * inv, yi[a] * inv);
    }
}

// ---------------- launch ----------------
extern "C" void kernel_launch(void* const* d_in, const int* in_sizes, int n_in,
                              void* d_out, int out_size) {
    const float* u    = (const float*)d_in[0];
    const float* kk   = (const float*)d_in[1];
    const float* gW[6];  for (int i = 0; i < 6; i++) gW[i]  = (const float*)d_in[2 + i];
    const float* dW[6];  for (int i = 0; i < 6; i++) dW[i]  = (const float*)d_in[8 + i];
    const float* frW[6]; for (int i = 0; i < 6; i++) frW[i] = (const float*)d_in[14 + i];
    const float* fiW[6]; for (int i = 0; i < 6; i++) fiW[i] = (const float*)d_in[20 + i];
    const float* bias = (const float*)d_in[26];
    float* out = (float*)d_out;

    // fused: G/D MLPs + iteration-0 row pass (du + rfft_W -> Uf)
    k_gdf<<<NROW, 256>>>(kk, u,
        gW[0], gW[1], gW[2], gW[3], gW[4], gW[5],
        dW[0], dW[1], dW[2], dW[3], dW[4], dW[5]);
    k_filt<<<129, 256>>>(
        frW[0], frW[1], frW[2], frW[3], frW[4], frW[5],
        fiW[0], fiW[1], fiW[2], fiW[3], fiW[4], fiW[5]);

    for (int it = 0; it < 4; it++) {
        k_col<<<4 * 129, 512>>>();
        if (it < 3) {
            k_row<1><<<NROW, 256>>>(it == 0 ? u : nullptr, nullptr, nullptr);
        } else {
            k_row<2><<<NROW, 256>>>(nullptr, bias, out);
        }
    }
}

// round 15
// speedup vs baseline: 1.0856x; 1.0152x over previous
#include <cuda_runtime.h>
#include <cuda_fp16.h>
#include <cstddef>
#include <math.h>

// Problem constants: N=4, H=W=256, C=8, CK=2, ITER=4, HID=16, C2=64.
#define NROW 1024            // n*256+h rows
#define TS 260               // per-transform smem stride (floats)

// Bank-conflict-free smem permutation for the radix-4 Stockham access sets.
// P(i) = i ^ ((i>>2)&28): invertible, preserves aligned 4-blocks.
__device__ __forceinline__ int PSW(int i) { return i ^ ((i >> 2) & 28); }

// ---------------- device scratch (no allocations allowed) ----------------
// gmat/dmat: [row][j][w][p]  p=half2 pair over k  (1024*8*256*4 half2 = 33.5MB each)
__device__ __align__(16) __half2 d_gmat[8388608];
__device__ __align__(16) __half2 d_dmat[8388608];
// filt: [wf][g][j][hf][q]  g=kk-half, q=0..3 -> kk=4g+q   (129*2*8*256*4 half2 = 8.45MB)
__device__ __align__(16) __half2 d_filt[(size_t)129 * 2 * 8 * 256 * 4];
__device__ __align__(16) float2 d_uf[(size_t)1024 * 129 * 8]; // [row][wf][c]
__device__ __align__(16) float  d_u[(size_t)1024 * 256 * 8];  // iterated field

__device__ __forceinline__ __half2 u2h(unsigned u) {
    __half2 h; *reinterpret_cast<unsigned*>(&h) = u; return h;
}
__device__ __forceinline__ unsigned h2u(__half2 h) {
    return *reinterpret_cast<unsigned*>(&h);
}

// ---------------- f32x2 packed math (sm_100+) ----------------
__device__ __forceinline__ unsigned long long pk2(float a, float b) {
    unsigned long long r;
    asm("mov.b64 %0, {%1, %2};" : "=l"(r) : "r"(__float_as_uint(a)), "r"(__float_as_uint(b)));
    return r;
}
__device__ __forceinline__ float2 upk2(unsigned long long v) {
    unsigned lo, hi;
    asm("mov.b64 {%0, %1}, %2;" : "=r"(lo), "=r"(hi) : "l"(v));
    return make_float2(__uint_as_float(lo), __uint_as_float(hi));
}
__device__ __forceinline__ unsigned long long fma2(unsigned long long a,
                                                   unsigned long long b,
                                                   unsigned long long c) {
    unsigned long long d;
    asm("fma.rn.f32x2 %0, %1, %2, %3;" : "=l"(d) : "l"(a), "l"(b), "l"(c));
    return d;
}

// ---------------- helpers ----------------
__device__ __forceinline__ float gelu_t(float x) {
    // exact tanhf — used in the iterated/output path only
    float inner = 0.7978845608028654f * (x + 0.044715f * x * x * x);
    return 0.5f * x * (1.0f + tanhf(inner));
}
__device__ __forceinline__ float gelu_a(float x) {
    // tanh.approx.f32 — setup MLPs only (error ~2^-11, below fp16 storage rounding)
    float inner = 0.7978845608028654f * (x + 0.044715f * x * x * x);
    float t;
    asm("tanh.approx.f32 %0, %1;" : "=f"(t) : "f"(inner));
    return 0.5f * x * (1.0f + t);
}

// MLP weights packed: w1[32]@0, b1[16]@32, w2[256]@48, b2[16]@304, w3[1024]@320, b3[64]@1344
__device__ __forceinline__ void load_mlp_w(float* dst,
    const float* w1, const float* b1, const float* w2, const float* b2,
    const float* w3, const float* b3, int tid, int nthr) {
    for (int i = tid; i < 32;   i += nthr) dst[i]        = w1[i];
    for (int i = tid; i < 16;   i += nthr) dst[32 + i]   = b1[i];
    for (int i = tid; i < 256;  i += nthr) dst[48 + i]   = w2[i];
    for (int i = tid; i < 16;   i += nthr) dst[304 + i]  = b2[i];
    for (int i = tid; i < 1024; i += nthr) dst[320 + i]  = w3[i];
    for (int i = tid; i < 64;   i += nthr) dst[1344 + i] = b3[i];
}

// 2-input MLP through the second gelu layer; f32x2 packed h2 layer + approx gelu.
// Outputs h2p[16]: each h2 value duplicated into a packed f32x2 multiplier.
__device__ __forceinline__ void mlp2_h2p(const float* __restrict__ Wm, float x0, float x1,
                                         unsigned long long* h2p) {
    unsigned long long h1p[16];
#pragma unroll
    for (int o = 0; o < 16; o++) {
        float h = gelu_a(fmaf(x0, Wm[o], fmaf(x1, Wm[16 + o], Wm[32 + o])));
        h1p[o] = pk2(h, h);
    }
#pragma unroll
    for (int o = 0; o < 16; o += 2) {
        const float2 bv = *reinterpret_cast<const float2*>(&Wm[304 + o]);
        unsigned long long acc = pk2(bv.x, bv.y);
#pragma unroll
        for (int i = 0; i < 16; i++) {
            float2 wv = *reinterpret_cast<const float2*>(&Wm[48 + i * 16 + o]);
            acc = fma2(h1p[i], pk2(wv.x, wv.y), acc);
        }
        float2 r = upk2(acc);
        float a0 = gelu_a(r.x), a1 = gelu_a(r.y);
        h2p[o]     = pk2(a0, a0);
        h2p[o + 1] = pk2(a1, a1);
    }
}

// In-smem Stockham radix-4 FFT, length 256, nf transforms at stride TS,
// all smem indices permuted by PSW (conflict-free). NT = threads cooperating.
// tw[t] = exp(-2*pi*i*t/256). sign=+1 forward, sign=-1 unnormalized inverse.
// Caller syncs before. Result ends in xr/xi (4 swaps).
template <int NT>
__device__ __forceinline__ void fft4_stages(float* xr, float* xi, float* yr, float* yi,
                                            const float2* __restrict__ tw,
                                            int nf, int tid, float sign) {
    float *ar = xr, *ai = xi, *br = yr, *bi = yi;
#pragma unroll
    for (int s = 0; s < 4; s++) {
        int m = 1 << (2 * s);            // 1,4,16,64
        for (int t0 = tid; t0 < nf * 64; t0 += NT) {
            int base = (t0 >> 6) * TS;
            int t = t0 & 63;
            int jm = t & ~(m - 1);
            int r  = t & (m - 1);
            float2 w1v = tw[jm];
            float2 w2v = tw[2 * jm];
            float w1r = w1v.x, w1i = sign * w1v.y;
            float w2r = w2v.x, w2i = sign * w2v.y;

            float Ar = ar[base + PSW(t)],       Ai = ai[base + PSW(t)];
            float Br = ar[base + PSW(t + 64)],  Bi = ai[base + PSW(t + 64)];
            float Cr = ar[base + PSW(t + 128)], Ci = ai[base + PSW(t + 128)];
            float Dr = ar[base + PSW(t + 192)], Di = ai[base + PSW(t + 192)];

            float s0r = Ar + Cr, s0i = Ai + Ci;
            float d0r = Ar - Cr, d0i = Ai - Ci;
            float s2r = Br + Dr, s2i = Bi + Di;
            float d1r = Br - Dr, d1i = Bi - Di;
            float s1r = w1r * d0r - w1i * d0i;
            float s1i = w1r * d0i + w1i * d0r;
            float er = sign * d1i, ei = -sign * d1r;
            float s3r = w1r * er - w1i * ei;
            float s3i = w1r * ei + w1i * er;

            float u0r = s0r - s2r, u0i = s0i - s2i;
            float u1r = s1r - s3r, u1i = s1i - s3i;
            float o2r = w2r * u0r - w2i * u0i;
            float o2i = w2r * u0i + w2i * u0r;
            float o3r = w2r * u1r - w2i * u1i;
            float o3i = w2r * u1i + w2i * u1r;

            if (s == 0) {
                // m=1: contiguous outputs -> one float4 store per array
                int o = base + PSW(4 * t);
                *reinterpret_cast<float4*>(br + o) =
                    make_float4(s0r + s2r, s1r + s3r, o2r, o3r);
                *reinterpret_cast<float4*>(bi + o) =
                    make_float4(s0i + s2i, s1i + s3i, o2i, o3i);
            } else {
                int o = 4 * jm + r;
                br[base + PSW(o)]         = s0r + s2r;
                bi[base + PSW(o)]         = s0i + s2i;
                br[base + PSW(o + m)]     = s1r + s3r;
                bi[base + PSW(o + m)]     = s1i + s3i;
                br[base + PSW(o + 2 * m)] = o2r;
                bi[base + PSW(o + 2 * m)] = o2i;
                br[base + PSW(o + 3 * m)] = o3r;
                bi[base + PSW(o + 3 * m)] = o3i;
            }
        }
        __syncthreads();
        float* tp;
        tp = ar; ar = br; br = tp;
        tp = ai; ai = bi; bi = tp;
    }
}

__device__ __forceinline__ void fill_tw(float2* tws, int tid, int nthr) {
    for (int t = tid; t < 128; t += nthr) {
        float s, c;
        sincospif((float)t * (1.0f / 128.0f), &s, &c);
        tws[t] = make_float2(c, -s);
    }
}

// ---- shared tail: pack du, forward rfft_W, write Uf (used by k_gdf and k_row) ----
__device__ __forceinline__ void fwd_rfft_store(float* xr, float* xi, float* yr, float* yi,
                                               const float2* tws, const float* du,
                                               float2* ufrow, int tid) {
    int pw = PSW(tid);
#pragma unroll
    for (int p = 0; p < 4; p++) {
        xr[p * TS + pw] = du[2 * p];
        xi[p * TS + pw] = du[2 * p + 1];
    }
    __syncthreads();
    fft4_stages<256>(xr, xi, yr, yi, tws, 4, tid, 1.0f);    // forward
    if (tid <= 128) {
        int k2 = tid, m2 = (256 - k2) & 255;
        int pk2i = PSW(k2), pm2 = PSW(m2);
#pragma unroll
        for (int p = 0; p < 4; p++) {
            float Zr = xr[p * TS + pk2i], Zi = xi[p * TS + pk2i];
            float Qr = xr[p * TS + pm2], Qi = xi[p * TS + pm2];
            float2 A = make_float2(0.5f * (Zr + Qr), 0.5f * (Zi - Qi));
            float2 B = make_float2(0.5f * (Zi + Qi), 0.5f * (Qr - Zr));
            ufrow[k2 * 8 + 2 * p]     = A;
            ufrow[k2 * 8 + 2 * p + 1] = B;
        }
    }
}

// ---------------- kernel A (fused): G/D MLPs + iteration-0 du + rfft_W -> Uf --------
// Thread w owns pixel (row, w): it computes the full fp32 D matrix for that pixel,
// so du = u @ D is formed in-register from fp32 values (no fp16 roundtrip, no
// re-read of dmat). This replaces the former k_row<0> launch entirely.
__global__ __launch_bounds__(256) void k_gdf(const float* __restrict__ kin,
    const float* __restrict__ uin,
    const float* gw1, const float* gb1, const float* gw2, const float* gb2,
    const float* gw3, const float* gb3,
    const float* dw1, const float* db1, const float* dw2, const float* db2,
    const float* dw3, const float* db3) {
    __shared__ float Wg[1408], Wd[1408];
    __shared__ __align__(16) float xr[4 * TS], xi[4 * TS], yr[4 * TS], yi[4 * TS];
    __shared__ float2 tws[128];
    int tid = threadIdx.x;
    load_mlp_w(Wg, gw1, gb1, gw2, gb2, gw3, gb3, tid, 256);
    load_mlp_w(Wd, dw1, db1, dw2, db2, dw3, db3, tid, 256);
    fill_tw(tws, tid, 256);
    __syncthreads();

    int row = blockIdx.x;       // n*256 + h
    int w   = tid;
    int pix = row * 256 + w;
    float x0 = kin[pix * 2 + 0];
    float x1 = kin[pix * 2 + 1];

    float uu[8];
    {
        const float4* up = (const float4*)(uin + (size_t)row * 2048 + w * 8);
        float4 a = up[0], b = up[1];
        uu[0] = a.x; uu[1] = a.y; uu[2] = a.z; uu[3] = a.w;
        uu[4] = b.x; uu[5] = b.y; uu[6] = b.z; uu[7] = b.w;
    }

    unsigned long long h2p[16];
    const float inv64 = 1.0f / 64.0f;
    float du[8];
#pragma unroll
    for (int kk = 0; kk < 8; kk++) du[kk] = 0.0f;

    // delta MLP: store fp16 D, accumulate fp32 du = u @ D
    mlp2_h2p(Wd, x0, x1, h2p);
#pragma unroll
    for (int j = 0; j < 8; j++) {
        uint4 pk;
        unsigned* pku = &pk.x;
        float uj = uu[j];
#pragma unroll
        for (int p = 0; p < 4; p++) {
            int jk0 = j * 8 + 2 * p;
            const float2 bv = *reinterpret_cast<const float2*>(&Wd[1344 + jk0]);
            unsigned long long acc = pk2(bv.x, bv.y);
#pragma unroll
            for (int i = 0; i < 16; i++) {
                float2 wv = *reinterpret_cast<const float2*>(&Wd[320 + i * 64 + jk0]);
                acc = fma2(h2p[i], pk2(wv.x, wv.y), acc);
            }
            float2 r = upk2(acc);
            float v0 = r.x * inv64, v1 = r.y * inv64;
            du[2 * p]     = fmaf(uj, v0, du[2 * p]);
            du[2 * p + 1] = fmaf(uj, v1, du[2 * p + 1]);
            pku[p] = h2u(__floats2half2_rn(v0, v1));
        }
        *reinterpret_cast<uint4*>(d_dmat + ((size_t)(row * 8 + j) * 256 + w) * 4) = pk;
    }
    // gamma MLP: store fp16 G
    mlp2_h2p(Wg, x0, x1, h2p);
#pragma unroll
    for (int j = 0; j < 8; j++) {
        uint4 pk;
        unsigned* pku = &pk.x;
#pragma unroll
        for (int p = 0; p < 4; p++) {
            int jk0 = j * 8 + 2 * p;
            const float2 bv = *reinterpret_cast<const float2*>(&Wg[1344 + jk0]);
            unsigned long long acc = pk2(bv.x, bv.y);
#pragma unroll
            for (int i = 0; i < 16; i++) {
                float2 wv = *reinterpret_cast<const float2*>(&Wg[320 + i * 64 + jk0]);
                acc = fma2(h2p[i], pk2(wv.x, wv.y), acc);
            }
            float2 r = upk2(acc);
            pku[p] = h2u(__floats2half2_rn(r.x * inv64, r.y * inv64));
        }
        *reinterpret_cast<uint4*>(d_gmat + ((size_t)(row * 8 + j) * 256 + w) * 4) = pk;
    }

    // forward rfft_W of du -> Uf (iteration 0 row pass)
    float2* ufrow = d_uf + (size_t)row * 129 * 8;
    fwd_rfft_store(xr, xi, yr, yi, tws, du, ufrow, tid);
}

// ---------------- kernel B: spectral filter (fp16, [wf][g][j][hf][q], f32x2 MLP) ----
// MLP input (kx, ky) = (wf, signed(hf)). Scale = 1/64 only; the 1/65536 FFT
// normalization is applied in k_col's store (fp16 would underflow).
__global__ __launch_bounds__(256) void k_filt(
    const float* rw1, const float* rb1, const float* rw2, const float* rb2,
    const float* rw3, const float* rb3,
    const float* iw1, const float* ib1, const float* iw2, const float* ib2,
    const float* iw3, const float* ib3) {
    __shared__ float Wr[1408], Wi[1408];
    int tid = threadIdx.x;
    load_mlp_w(Wr, rw1, rb1, rw2, rb2, rw3, rb3, tid, 256);
    load_mlp_w(Wi, iw1, ib1, iw2, ib2, iw3, ib3, tid, 256);
    __syncthreads();

    int wf = blockIdx.x;
    int hf = tid;
    float x0 = (float)wf;
    float x1 = (float)(hf < 128 ? hf : hf - 256);
    unsigned long long h2rp[16], h2ip[16];
    mlp2_h2p(Wr, x0, x1, h2rp);
    mlp2_h2p(Wi, x0, x1, h2ip);
    const float sc = 1.0f / 64.0f;
#pragma unroll
    for (int g = 0; g < 2; g++) {
#pragma unroll
        for (int j = 0; j < 8; j++) {
            uint4 pk;
            unsigned* pku = &pk.x;
#pragma unroll
            for (int qq = 0; qq < 2; qq++) {           // pairs (q=2qq, 2qq+1)
                int jk0 = j * 8 + 4 * g + 2 * qq;
                const float2 bvr = *reinterpret_cast<const float2*>(&Wr[1344 + jk0]);
                const float2 bvi = *reinterpret_cast<const float2*>(&Wi[1344 + jk0]);
                unsigned long long accr = pk2(bvr.x, bvr.y);
                unsigned long long acci = pk2(bvi.x, bvi.y);
#pragma unroll
                for (int i = 0; i < 16; i++) {
                    float2 wvr = *reinterpret_cast<const float2*>(&Wr[320 + i * 64 + jk0]);
                    float2 wvi = *reinterpret_cast<const float2*>(&Wi[320 + i * 64 + jk0]);
                    accr = fma2(h2rp[i], pk2(wvr.x, wvr.y), accr);
                    acci = fma2(h2ip[i], pk2(wvi.x, wvi.y), acci);
                }
                float2 rr = upk2(accr);
                float2 ri = upk2(acci);
                pku[2 * qq]     = h2u(__floats2half2_rn(rr.x * sc, ri.x * sc));
                pku[2 * qq + 1] = h2u(__floats2half2_rn(rr.y * sc, ri.y * sc));
            }
            size_t idx = ((((size_t)wf * 2 + g) * 8 + j) * 256 + hf) * 4;
            *reinterpret_cast<uint4*>(d_filt + idx) = pk;
        }
    }
}

// ---------------- row pass (iterations 1..) ----------------
// MODE 1: gu = irfft_W(Uf) ; u' = 2u + (gu-u)@G -> d_u ; du = u'@D ; rfft_W -> Uf
// MODE 2: gu = irfft_W(Uf) ; u' = 2u + (gu-u)@G ; out = gelu(u'+bias)
// (256,4) bound is load-bearing: R8/R9/R13 measured regs=64 @ ~25us; without it
// ptxas went to 80 regs / occ 31% / 28.7us (R12).
// cp.async prefetch: G[j=0..3] (16KB) is fetched into smem during the inverse
// FFT (loads are independent of FFT data; ptxas can't hoist LDG across BAR).
// Each thread reads only its own prefetched slots -> wait_group 0, no barrier.
template <int MODE>
__global__ __launch_bounds__(256, 4) void k_row(const float* __restrict__ uin,
                                                const float* __restrict__ bias,
                                                float* __restrict__ outp) {
    __shared__ __align__(16) float xr[4 * TS], xi[4 * TS], yr[4 * TS], yi[4 * TS];
    __shared__ float2 tws[128];
    __shared__ __align__(16) uint4 sG[4 * 256];   // G[j=0..3][w], 16KB

    int tid = threadIdx.x;
    int row = blockIdx.x;                       // n*256 + h
    fill_tw(tws, tid, 256);

    float2* ufrow = d_uf + (size_t)row * 129 * 8;
    const float* ubase = (uin != nullptr) ? uin : d_u;
    const float* urow  = ubase + (size_t)row * 2048;

    float unew[8];
    int w = tid;

    const __half2* G = d_gmat + (size_t)row * 8 * 1024 + w * 4;
    // issue async prefetch of G[j=0..3] before the FFT phase
    {
#pragma unroll
        for (int j = 0; j < 4; j++) {
            unsigned dst = (unsigned)__cvta_generic_to_shared(&sG[j * 256 + w]);
            asm volatile("cp.async.cg.shared.global [%0], [%1], 16;"
                         :: "r"(dst), "l"(G + (size_t)j * 1024) : "memory");
        }
        asm volatile("cp.async.commit_group;" ::: "memory");
    }

    {
        // coalesced load of this thread's spectrum column (64B);
        // drop Im at DC/Nyquist (c2r semantics); Hermitian pack into xr/xi.
        int wfL = (tid <= 128) ? tid : 256 - tid;
        const float4* up = (const float4*)(ufrow + wfL * 8);
        float4 q0 = up[0], q1 = up[1], q2 = up[2], q3 = up[3];
        if (wfL == 0 || wfL == 128) {
            q0.y = 0.0f; q0.w = 0.0f; q1.y = 0.0f; q1.w = 0.0f;
            q2.y = 0.0f; q2.w = 0.0f; q3.y = 0.0f; q3.w = 0.0f;
        }
        float4 qs[4] = {q0, q1, q2, q3};
        int pt = PSW(tid);
        if (tid <= 128) {
#pragma unroll
            for (int p = 0; p < 4; p++) {
                xr[p * TS + pt] = qs[p].x - qs[p].w;   // A.x - B.y
                xi[p * TS + pt] = qs[p].y + qs[p].z;   // A.y + B.x
            }
        } else {
#pragma unroll
            for (int p = 0; p < 4; p++) {
                xr[p * TS + pt] = qs[p].x + qs[p].w;   // A.x + B.y
                xi[p * TS + pt] = qs[p].z - qs[p].y;   // B.x - A.y
            }
        }
        __syncthreads();
        fft4_stages<256>(xr, xi, yr, yi, tws, 4, tid, -1.0f);   // inverse (unnormalized)

        float gu[8], uu[8];
        int pw = PSW(w);
#pragma unroll
        for (int p = 0; p < 4; p++) {
            gu[2 * p]     = xr[p * TS + pw];
            gu[2 * p + 1] = xi[p * TS + pw];
        }
        {
            const float4* upu = (const float4*)(urow + w * 8);
            float4 a = upu[0], b = upu[1];
            uu[0] = a.x; uu[1] = a.y; uu[2] = a.z; uu[3] = a.w;
            uu[4] = b.x; uu[5] = b.y; uu[6] = b.z; uu[7] = b.w;
        }
        float tv[8];
#pragma unroll
        for (int j = 0; j < 8; j++) tv[j] = gu[j] - uu[j];
#pragma unroll
        for (int kk = 0; kk < 8; kk++) unew[kk] = 2.0f * uu[kk];

        // wait for prefetched G[j<4]; each thread reads only its own slots.
        asm volatile("cp.async.wait_group 0;" ::: "memory");
#pragma unroll
        for (int j = 0; j < 8; j++) {
            float tj = tv[j];
            uint4 raw = (j < 4) ? sG[j * 256 + w]
                                : *reinterpret_cast<const uint4*>(G + (size_t)j * 1024);
            float2 g0 = __half22float2(u2h(raw.x));
            float2 g1 = __half22float2(u2h(raw.y));
            float2 g2 = __half22float2(u2h(raw.z));
            float2 g3 = __half22float2(u2h(raw.w));
            unew[0] = fmaf(tj, g0.x, unew[0]); unew[1] = fmaf(tj, g0.y, unew[1]);
            unew[2] = fmaf(tj, g1.x, unew[2]); unew[3] = fmaf(tj, g1.y, unew[3]);
            unew[4] = fmaf(tj, g2.x, unew[4]); unew[5] = fmaf(tj, g2.y, unew[5]);
            unew[6] = fmaf(tj, g3.x, unew[6]); unew[7] = fmaf(tj, g3.y, unew[7]);
        }
        if (MODE == 2) {
            float4 o0, o1;
            o0.x = gelu_t(unew[0] + bias[0]);
            o0.y = gelu_t(unew[1] + bias[1]);
            o0.z = gelu_t(unew[2] + bias[2]);
            o0.w = gelu_t(unew[3] + bias[3]);
            o1.x = gelu_t(unew[4] + bias[4]);
            o1.y = gelu_t(unew[5] + bias[5]);
            o1.z = gelu_t(unew[6] + bias[6]);
            o1.w = gelu_t(unew[7] + bias[7]);
            float4* op = (float4*)(outp + (size_t)row * 2048 + w * 8);
            op[0] = o0; op[1] = o1;
            return;
        }
        // MODE 1: persist u'
        {
            float4 o0, o1;
            o0.x = unew[0]; o0.y = unew[1]; o0.z = unew[2]; o0.w = unew[3];
            o1.x = unew[4]; o1.y = unew[5]; o1.z = unew[6]; o1.w = unew[7];
            float4* op = (float4*)(d_u + (size_t)row * 2048 + w * 8);
            op[0] = o0; op[1] = o1;
        }
    }

    // du = unew @ D ; pack ; forward FFT ; unpack rfft ; write Uf
    {
        const __half2* D = d_dmat + (size_t)row * 8 * 1024 + w * 4;
        float du[8];
#pragma unroll
        for (int kk = 0; kk < 8; kk++) du[kk] = 0.0f;
#pragma unroll
        for (int j = 0; j < 8; j++) {
            float uj = unew[j];
            uint4 raw = *reinterpret_cast<const uint4*>(D + (size_t)j * 1024);
            float2 g0 = __half22float2(u2h(raw.x));
            float2 g1 = __half22float2(u2h(raw.y));
            float2 g2 = __half22float2(u2h(raw.z));
            float2 g3 = __half22float2(u2h(raw.w));
            du[0] = fmaf(uj, g0.x, du[0]); du[1] = fmaf(uj, g0.y, du[1]);
            du[2] = fmaf(uj, g1.x, du[2]); du[3] = fmaf(uj, g1.y, du[3]);
            du[4] = fmaf(uj, g2.x, du[4]); du[5] = fmaf(uj, g2.y, du[5]);
            du[6] = fmaf(uj, g3.x, du[6]); du[7] = fmaf(uj, g3.y, du[7]);
        }
        __syncthreads();   // all gu reads of xr/xi complete
        fwd_rfft_store(xr, xi, yr, yi, tws, du, ufrow, tid);
    }
}

// ---------------- column pass: FFT_H, filter matvec, IFFT_H (in-place on Uf) ---------
// 512 threads: one butterfly per thread per stage; matvec split by kk-half.
// (512,2): ~64 regs -> 2 blocks/SM (32 warps). Measured win in R14 (-9us total);
// R8's regression was the per-block n-loop, not the cap.
__global__ __launch_bounds__(512, 2) void k_col() {
    __shared__ __align__(16) float xr[8 * TS], xi[8 * TS], yr[8 * TS], yi[8 * TS];
    __shared__ float2 tws[128];
    int tid = threadIdx.x;
    int wf = blockIdx.x % 129;
    int n  = blockIdx.x / 129;
    fill_tw(tws, tid, 512);

    float2* base = d_uf + ((size_t)n * 256 * 129 + wf) * 8;  // + h*129*8 + c
    for (int it = 0; it < 4; it++) {
        int idx = it * 512 + tid;
        int h = idx >> 3, c = idx & 7;
        float2 v = base[(size_t)h * 129 * 8 + c];
        int a = c * TS + PSW(h);
        xr[a] = v.x;
        xi[a] = v.y;
    }
    __syncthreads();
    fft4_stages<512>(xr, xi, yr, yi, tws, 8, tid, 1.0f);     // forward along H

    int hf = tid & 255;
    int g  = tid >> 8;          // kk-half
    int ph = PSW(hf);
    float vr[4], vi[4];
#pragma unroll
    for (int q = 0; q < 4; q++) { vr[q] = 0.0f; vi[q] = 0.0f; }
    const __half2* F = d_filt + (((size_t)wf * 2 + g) * 8 * 256 + hf) * 4;
#pragma unroll
    for (int j = 0; j < 8; j++) {
        float zr = xr[j * TS + ph], zi = xi[j * TS + ph];
        uint4 fa = *reinterpret_cast<const uint4*>(F + (size_t)j * 1024);
        const unsigned* fu = &fa.x;
#pragma unroll
        for (int q = 0; q < 4; q++) {
            float2 f = __half22float2(u2h(fu[q]));
            vr[q] = fmaf(zr, f.x, fmaf(-zi, f.y, vr[q]));
            vi[q] = fmaf(zr, f.y, fmaf(zi, f.x, vi[q]));
        }
    }
    __syncthreads();
#pragma unroll
    for (int q = 0; q < 4; q++) {
        int kk = 4 * g + q;
        yr[kk * TS + ph] = vr[q];
        yi[kk * TS + ph] = vi[q];
    }
    __syncthreads();
    fft4_stages<512>(yr, yi, xr, xi, tws, 8, tid, -1.0f);    // inverse (unnormalized)

    const float inv = 1.0f / 65536.0f;  // both inverse-FFT norms (kept out of fp16 filt)
    for (int it = 0; it < 4; it++) {
        int idx = it * 512 + tid;
        int h = idx >> 3, c = idx & 7;
        int a = c * TS + PSW(h);
        base[(size_t)h * 129 * 8 + c] = make_float2(yr[a] * inv, yi[a] * inv);
    }
}

// ---------------- launch ----------------
extern "C" void kernel_launch(void* const* d_in, const int* in_sizes, int n_in,
                              void* d_out, int out_size) {
    const float* u    = (const float*)d_in[0];
    const float* kk   = (const float*)d_in[1];
    const float* gW[6];  for (int i = 0; i < 6; i++) gW[i]  = (const float*)d_in[2 + i];
    const float* dW[6];  for (int i = 0; i < 6; i++) dW[i]  = (const float*)d_in[8 + i];
    const float* frW[6]; for (int i = 0; i < 6; i++) frW[i] = (const float*)d_in[14 + i];
    const float* fiW[6]; for (int i = 0; i < 6; i++) fiW[i] = (const float*)d_in[20 + i];
    const float* bias = (const float*)d_in[26];
    float* out = (float*)d_out;

    // fused: G/D MLPs + iteration-0 row pass (du + rfft_W -> Uf)
    k_gdf<<<NROW, 256>>>(kk, u,
        gW[0], gW[1], gW[2], gW[3], gW[4], gW[5],
        dW[0], dW[1], dW[2], dW[3], dW[4], dW[5]);
    k_filt<<<129, 256>>>(
        frW[0], frW[1], frW[2], frW[3], frW[4], frW[5],
        fiW[0], fiW[1], fiW[2], fiW[3], fiW[4], fiW[5]);

    for (int it = 0; it < 4; it++) {
        k_col<<<4 * 129, 512>>>();
        if (it < 3) {
            k_row<1><<<NROW, 256>>>(it == 0 ? u : nullptr, nullptr, nullptr);
        } else {
            k_row<2><<<NROW, 256>>>(nullptr, bias, out);
        }
    }
}

// round 16
// speedup vs baseline: 1.1056x; 1.0185x over previous
#include <cuda_runtime.h>
#include <cuda_fp16.h>
#include <cstddef>
#include <math.h>

// Problem constants: N=4, H=W=256, C=8, CK=2, ITER=4, HID=16, C2=64.
#define NROW 1024            // n*256+h rows
#define TS 260               // per-transform smem stride (floats)

// Bank-conflict-free smem permutation for the radix-4 Stockham access sets.
// P(i) = i ^ ((i>>2)&28): invertible, preserves aligned 4-blocks.
__device__ __forceinline__ int PSW(int i) { return i ^ ((i >> 2) & 28); }

// ---------------- device scratch (no allocations allowed) ----------------
// gmat/dmat: [row][j][w][p]  p=half2 pair over k  (1024*8*256*4 half2 = 33.5MB each)
__device__ __align__(16) __half2 d_gmat[8388608];
__device__ __align__(16) __half2 d_dmat[8388608];
// filt: [wf][g][j][hf][q]  g=kk-half, q=0..3 -> kk=4g+q   (129*2*8*256*4 half2 = 8.45MB)
__device__ __align__(16) __half2 d_filt[(size_t)129 * 2 * 8 * 256 * 4];
__device__ __align__(16) float2 d_uf[(size_t)1024 * 129 * 8]; // [row][wf][c]
__device__ __align__(16) float  d_u[(size_t)1024 * 256 * 8];  // iterated field

__device__ __forceinline__ __half2 u2h(unsigned u) {
    __half2 h; *reinterpret_cast<unsigned*>(&h) = u; return h;
}
__device__ __forceinline__ unsigned h2u(__half2 h) {
    return *reinterpret_cast<unsigned*>(&h);
}

// ---------------- f32x2 packed math (sm_100+) ----------------
__device__ __forceinline__ unsigned long long pk2(float a, float b) {
    unsigned long long r;
    asm("mov.b64 %0, {%1, %2};" : "=l"(r) : "r"(__float_as_uint(a)), "r"(__float_as_uint(b)));
    return r;
}
__device__ __forceinline__ float2 upk2(unsigned long long v) {
    unsigned lo, hi;
    asm("mov.b64 {%0, %1}, %2;" : "=r"(lo), "=r"(hi) : "l"(v));
    return make_float2(__uint_as_float(lo), __uint_as_float(hi));
}
__device__ __forceinline__ unsigned long long fma2(unsigned long long a,
                                                   unsigned long long b,
                                                   unsigned long long c) {
    unsigned long long d;
    asm("fma.rn.f32x2 %0, %1, %2, %3;" : "=l"(d) : "l"(a), "l"(b), "l"(c));
    return d;
}

// ---------------- helpers ----------------
__device__ __forceinline__ float gelu_t(float x) {
    // exact tanhf — used in the iterated/output path only
    float inner = 0.7978845608028654f * (x + 0.044715f * x * x * x);
    return 0.5f * x * (1.0f + tanhf(inner));
}
__device__ __forceinline__ float gelu_a(float x) {
    // tanh.approx.f32 — setup MLPs only (error ~2^-11, below fp16 storage rounding)
    float inner = 0.7978845608028654f * (x + 0.044715f * x * x * x);
    float t;
    asm("tanh.approx.f32 %0, %1;" : "=f"(t) : "f"(inner));
    return 0.5f * x * (1.0f + t);
}

// MLP weights packed: w1[32]@0, b1[16]@32, w2[256]@48, b2[16]@304, w3[1024]@320, b3[64]@1344
__device__ __forceinline__ void load_mlp_w(float* dst,
    const float* w1, const float* b1, const float* w2, const float* b2,
    const float* w3, const float* b3, int tid, int nthr) {
    for (int i = tid; i < 32;   i += nthr) dst[i]        = w1[i];
    for (int i = tid; i < 16;   i += nthr) dst[32 + i]   = b1[i];
    for (int i = tid; i < 256;  i += nthr) dst[48 + i]   = w2[i];
    for (int i = tid; i < 16;   i += nthr) dst[304 + i]  = b2[i];
    for (int i = tid; i < 1024; i += nthr) dst[320 + i]  = w3[i];
    for (int i = tid; i < 64;   i += nthr) dst[1344 + i] = b3[i];
}

// 2-input MLP through the second gelu layer; f32x2 packed h2 layer + approx gelu.
// Outputs h2p[16]: each h2 value duplicated into a packed f32x2 multiplier.
__device__ __forceinline__ void mlp2_h2p(const float* __restrict__ Wm, float x0, float x1,
                                         unsigned long long* h2p) {
    unsigned long long h1p[16];
#pragma unroll
    for (int o = 0; o < 16; o++) {
        float h = gelu_a(fmaf(x0, Wm[o], fmaf(x1, Wm[16 + o], Wm[32 + o])));
        h1p[o] = pk2(h, h);
    }
#pragma unroll
    for (int o = 0; o < 16; o += 2) {
        const float2 bv = *reinterpret_cast<const float2*>(&Wm[304 + o]);
        unsigned long long acc = pk2(bv.x, bv.y);
#pragma unroll
        for (int i = 0; i < 16; i++) {
            float2 wv = *reinterpret_cast<const float2*>(&Wm[48 + i * 16 + o]);
            acc = fma2(h1p[i], pk2(wv.x, wv.y), acc);
        }
        float2 r = upk2(acc);
        float a0 = gelu_a(r.x), a1 = gelu_a(r.y);
        h2p[o]     = pk2(a0, a0);
        h2p[o + 1] = pk2(a1, a1);
    }
}

// In-smem Stockham radix-4 FFT, length 256, nf transforms at stride TS,
// all smem indices permuted by PSW (conflict-free). NT = threads cooperating.
// tw[t] = exp(-2*pi*i*t/256). sign=+1 forward, sign=-1 unnormalized inverse.
// Caller syncs before. Result ends in xr/xi (4 swaps).
template <int NT>
__device__ __forceinline__ void fft4_stages(float* xr, float* xi, float* yr, float* yi,
                                            const float2* __restrict__ tw,
                                            int nf, int tid, float sign) {
    float *ar = xr, *ai = xi, *br = yr, *bi = yi;
#pragma unroll
    for (int s = 0; s < 4; s++) {
        int m = 1 << (2 * s);            // 1,4,16,64
        for (int t0 = tid; t0 < nf * 64; t0 += NT) {
            int base = (t0 >> 6) * TS;
            int t = t0 & 63;
            int jm = t & ~(m - 1);
            int r  = t & (m - 1);
            float2 w1v = tw[jm];
            float2 w2v = tw[2 * jm];
            float w1r = w1v.x, w1i = sign * w1v.y;
            float w2r = w2v.x, w2i = sign * w2v.y;

            float Ar = ar[base + PSW(t)],       Ai = ai[base + PSW(t)];
            float Br = ar[base + PSW(t + 64)],  Bi = ai[base + PSW(t + 64)];
            float Cr = ar[base + PSW(t + 128)], Ci = ai[base + PSW(t + 128)];
            float Dr = ar[base + PSW(t + 192)], Di = ai[base + PSW(t + 192)];

            float s0r = Ar + Cr, s0i = Ai + Ci;
            float d0r = Ar - Cr, d0i = Ai - Ci;
            float s2r = Br + Dr, s2i = Bi + Di;
            float d1r = Br - Dr, d1i = Bi - Di;
            float s1r = w1r * d0r - w1i * d0i;
            float s1i = w1r * d0i + w1i * d0r;
            float er = sign * d1i, ei = -sign * d1r;
            float s3r = w1r * er - w1i * ei;
            float s3i = w1r * ei + w1i * er;

            float u0r = s0r - s2r, u0i = s0i - s2i;
            float u1r = s1r - s3r, u1i = s1i - s3i;
            float o2r = w2r * u0r - w2i * u0i;
            float o2i = w2r * u0i + w2i * u0r;
            float o3r = w2r * u1r - w2i * u1i;
            float o3i = w2r * u1i + w2i * u1r;

            if (s == 0) {
                // m=1: contiguous outputs -> one float4 store per array
                int o = base + PSW(4 * t);
                *reinterpret_cast<float4*>(br + o) =
                    make_float4(s0r + s2r, s1r + s3r, o2r, o3r);
                *reinterpret_cast<float4*>(bi + o) =
                    make_float4(s0i + s2i, s1i + s3i, o2i, o3i);
            } else {
                int o = 4 * jm + r;
                br[base + PSW(o)]         = s0r + s2r;
                bi[base + PSW(o)]         = s0i + s2i;
                br[base + PSW(o + m)]     = s1r + s3r;
                bi[base + PSW(o + m)]     = s1i + s3i;
                br[base + PSW(o + 2 * m)] = o2r;
                bi[base + PSW(o + 2 * m)] = o2i;
                br[base + PSW(o + 3 * m)] = o3r;
                bi[base + PSW(o + 3 * m)] = o3i;
            }
        }
        __syncthreads();
        float* tp;
        tp = ar; ar = br; br = tp;
        tp = ai; ai = bi; bi = tp;
    }
}

__device__ __forceinline__ void fill_tw(float2* tws, int tid, int nthr) {
    for (int t = tid; t < 128; t += nthr) {
        float s, c;
        sincospif((float)t * (1.0f / 128.0f), &s, &c);
        tws[t] = make_float2(c, -s);
    }
}

// ---- shared tail: pack du, forward rfft_W, write Uf (used by k_gdf and k_row) ----
__device__ __forceinline__ void fwd_rfft_store(float* xr, float* xi, float* yr, float* yi,
                                               const float2* tws, const float* du,
                                               float2* ufrow, int tid) {
    int pw = PSW(tid);
#pragma unroll
    for (int p = 0; p < 4; p++) {
        xr[p * TS + pw] = du[2 * p];
        xi[p * TS + pw] = du[2 * p + 1];
    }
    __syncthreads();
    fft4_stages<256>(xr, xi, yr, yi, tws, 4, tid, 1.0f);    // forward
    if (tid <= 128) {
        int k2 = tid, m2 = (256 - k2) & 255;
        int pk2i = PSW(k2), pm2 = PSW(m2);
#pragma unroll
        for (int p = 0; p < 4; p++) {
            float Zr = xr[p * TS + pk2i], Zi = xi[p * TS + pk2i];
            float Qr = xr[p * TS + pm2], Qi = xi[p * TS + pm2];
            float2 A = make_float2(0.5f * (Zr + Qr), 0.5f * (Zi - Qi));
            float2 B = make_float2(0.5f * (Zi + Qi), 0.5f * (Qr - Zr));
            ufrow[k2 * 8 + 2 * p]     = A;
            ufrow[k2 * 8 + 2 * p + 1] = B;
        }
    }
}

// ---------------- kernel A (fused): G/D MLPs + iteration-0 du + rfft_W -> Uf --------
// Thread w owns pixel (row, w): it computes the full fp32 D matrix for that pixel,
// so du = u @ D is formed in-register from fp32 values (no fp16 roundtrip, no
// re-read of dmat). This replaces the former k_row<0> launch entirely.
__global__ __launch_bounds__(256) void k_gdf(const float* __restrict__ kin,
    const float* __restrict__ uin,
    const float* gw1, const float* gb1, const float* gw2, const float* gb2,
    const float* gw3, const float* gb3,
    const float* dw1, const float* db1, const float* dw2, const float* db2,
    const float* dw3, const float* db3) {
    __shared__ float Wg[1408], Wd[1408];
    __shared__ __align__(16) float xr[4 * TS], xi[4 * TS], yr[4 * TS], yi[4 * TS];
    __shared__ float2 tws[128];
    int tid = threadIdx.x;
    load_mlp_w(Wg, gw1, gb1, gw2, gb2, gw3, gb3, tid, 256);
    load_mlp_w(Wd, dw1, db1, dw2, db2, dw3, db3, tid, 256);
    fill_tw(tws, tid, 256);
    __syncthreads();

    int row = blockIdx.x;       // n*256 + h
    int w   = tid;
    int pix = row * 256 + w;
    float x0 = kin[pix * 2 + 0];
    float x1 = kin[pix * 2 + 1];

    float uu[8];
    {
        const float4* up = (const float4*)(uin + (size_t)row * 2048 + w * 8);
        float4 a = up[0], b = up[1];
        uu[0] = a.x; uu[1] = a.y; uu[2] = a.z; uu[3] = a.w;
        uu[4] = b.x; uu[5] = b.y; uu[6] = b.z; uu[7] = b.w;
    }

    unsigned long long h2p[16];
    const float inv64 = 1.0f / 64.0f;
    float du[8];
#pragma unroll
    for (int kk = 0; kk < 8; kk++) du[kk] = 0.0f;

    // delta MLP: store fp16 D, accumulate fp32 du = u @ D
    mlp2_h2p(Wd, x0, x1, h2p);
#pragma unroll
    for (int j = 0; j < 8; j++) {
        uint4 pk;
        unsigned* pku = &pk.x;
        float uj = uu[j];
#pragma unroll
        for (int p = 0; p < 4; p++) {
            int jk0 = j * 8 + 2 * p;
            const float2 bv = *reinterpret_cast<const float2*>(&Wd[1344 + jk0]);
            unsigned long long acc = pk2(bv.x, bv.y);
#pragma unroll
            for (int i = 0; i < 16; i++) {
                float2 wv = *reinterpret_cast<const float2*>(&Wd[320 + i * 64 + jk0]);
                acc = fma2(h2p[i], pk2(wv.x, wv.y), acc);
            }
            float2 r = upk2(acc);
            float v0 = r.x * inv64, v1 = r.y * inv64;
            du[2 * p]     = fmaf(uj, v0, du[2 * p]);
            du[2 * p + 1] = fmaf(uj, v1, du[2 * p + 1]);
            pku[p] = h2u(__floats2half2_rn(v0, v1));
        }
        *reinterpret_cast<uint4*>(d_dmat + ((size_t)(row * 8 + j) * 256 + w) * 4) = pk;
    }
    // gamma MLP: store fp16 G
    mlp2_h2p(Wg, x0, x1, h2p);
#pragma unroll
    for (int j = 0; j < 8; j++) {
        uint4 pk;
        unsigned* pku = &pk.x;
#pragma unroll
        for (int p = 0; p < 4; p++) {
            int jk0 = j * 8 + 2 * p;
            const float2 bv = *reinterpret_cast<const float2*>(&Wg[1344 + jk0]);
            unsigned long long acc = pk2(bv.x, bv.y);
#pragma unroll
            for (int i = 0; i < 16; i++) {
                float2 wv = *reinterpret_cast<const float2*>(&Wg[320 + i * 64 + jk0]);
                acc = fma2(h2p[i], pk2(wv.x, wv.y), acc);
            }
            float2 r = upk2(acc);
            pku[p] = h2u(__floats2half2_rn(r.x * inv64, r.y * inv64));
        }
        *reinterpret_cast<uint4*>(d_gmat + ((size_t)(row * 8 + j) * 256 + w) * 4) = pk;
    }

    // forward rfft_W of du -> Uf (iteration 0 row pass)
    float2* ufrow = d_uf + (size_t)row * 129 * 8;
    fwd_rfft_store(xr, xi, yr, yi, tws, du, ufrow, tid);
}

// ---------------- kernel B: spectral filter (fp16, [wf][g][j][hf][q], f32x2 MLP) ----
// MLP input (kx, ky) = (wf, signed(hf)). Scale = 1/64 only; the 1/65536 FFT
// normalization is applied in k_col's store (fp16 would underflow).
__global__ __launch_bounds__(256) void k_filt(
    const float* rw1, const float* rb1, const float* rw2, const float* rb2,
    const float* rw3, const float* rb3,
    const float* iw1, const float* ib1, const float* iw2, const float* ib2,
    const float* iw3, const float* ib3) {
    __shared__ float Wr[1408], Wi[1408];
    int tid = threadIdx.x;
    load_mlp_w(Wr, rw1, rb1, rw2, rb2, rw3, rb3, tid, 256);
    load_mlp_w(Wi, iw1, ib1, iw2, ib2, iw3, ib3, tid, 256);
    __syncthreads();

    int wf = blockIdx.x;
    int hf = tid;
    float x0 = (float)wf;
    float x1 = (float)(hf < 128 ? hf : hf - 256);
    unsigned long long h2rp[16], h2ip[16];
    mlp2_h2p(Wr, x0, x1, h2rp);
    mlp2_h2p(Wi, x0, x1, h2ip);
    const float sc = 1.0f / 64.0f;
#pragma unroll
    for (int g = 0; g < 2; g++) {
#pragma unroll
        for (int j = 0; j < 8; j++) {
            uint4 pk;
            unsigned* pku = &pk.x;
#pragma unroll
            for (int qq = 0; qq < 2; qq++) {           // pairs (q=2qq, 2qq+1)
                int jk0 = j * 8 + 4 * g + 2 * qq;
                const float2 bvr = *reinterpret_cast<const float2*>(&Wr[1344 + jk0]);
                const float2 bvi = *reinterpret_cast<const float2*>(&Wi[1344 + jk0]);
                unsigned long long accr = pk2(bvr.x, bvr.y);
                unsigned long long acci = pk2(bvi.x, bvi.y);
#pragma unroll
                for (int i = 0; i < 16; i++) {
                    float2 wvr = *reinterpret_cast<const float2*>(&Wr[320 + i * 64 + jk0]);
                    float2 wvi = *reinterpret_cast<const float2*>(&Wi[320 + i * 64 + jk0]);
                    accr = fma2(h2rp[i], pk2(wvr.x, wvr.y), accr);
                    acci = fma2(h2ip[i], pk2(wvi.x, wvi.y), acci);
                }
                float2 rr = upk2(accr);
                float2 ri = upk2(acci);
                pku[2 * qq]     = h2u(__floats2half2_rn(rr.x * sc, ri.x * sc));
                pku[2 * qq + 1] = h2u(__floats2half2_rn(rr.y * sc, ri.y * sc));
            }
            size_t idx = ((((size_t)wf * 2 + g) * 8 + j) * 256 + hf) * 4;
            *reinterpret_cast<uint4*>(d_filt + idx) = pk;
        }
    }
}

// ---------------- row pass (iterations 1..) ----------------
// MODE 1: gu = irfft_W(Uf) ; u' = 2u + (gu-u)@G -> d_u ; du = u'@D ; rfft_W -> Uf
// MODE 2: gu = irfft_W(Uf) ; u' = 2u + (gu-u)@G ; out = gelu(u'+bias)
// (256,4) bound is load-bearing: R8/R9/R13 measured regs=64 @ ~25us; without it
// ptxas went to 80 regs / occ 31% / 28.7us (R12).
// cp.async prefetch: G[j=0..3] (16KB) + (MODE 1) D[j=0..2] (12KB) fetched into
// smem during the inverse FFT (addresses independent of FFT data; ptxas can't
// hoist LDG across BAR). Each thread reads only its own prefetched slots ->
// wait_group 0, no barrier. smem total 46.3KB < 48KB static limit.
template <int MODE>
__global__ __launch_bounds__(256, 4) void k_row(const float* __restrict__ uin,
                                                const float* __restrict__ bias,
                                                float* __restrict__ outp) {
    __shared__ __align__(16) float xr[4 * TS], xi[4 * TS], yr[4 * TS], yi[4 * TS];
    __shared__ float2 tws[128];
    __shared__ __align__(16) uint4 sG[4 * 256];   // G[j=0..3][w], 16KB
    __shared__ __align__(16) uint4 sD[3 * 256];   // D[j=0..2][w], 12KB (MODE 1 only)

    int tid = threadIdx.x;
    int row = blockIdx.x;                       // n*256 + h
    fill_tw(tws, tid, 256);

    float2* ufrow = d_uf + (size_t)row * 129 * 8;
    const float* ubase = (uin != nullptr) ? uin : d_u;
    const float* urow  = ubase + (size_t)row * 2048;

    float unew[8];
    int w = tid;

    const __half2* G = d_gmat + (size_t)row * 8 * 1024 + w * 4;
    const __half2* D = d_dmat + (size_t)row * 8 * 1024 + w * 4;
    // issue async prefetches before the FFT phase
    {
#pragma unroll
        for (int j = 0; j < 4; j++) {
            unsigned dst = (unsigned)__cvta_generic_to_shared(&sG[j * 256 + w]);
            asm volatile("cp.async.cg.shared.global [%0], [%1], 16;"
                         :: "r"(dst), "l"(G + (size_t)j * 1024) : "memory");
        }
        if (MODE == 1) {
#pragma unroll
            for (int j = 0; j < 3; j++) {
                unsigned dst = (unsigned)__cvta_generic_to_shared(&sD[j * 256 + w]);
                asm volatile("cp.async.cg.shared.global [%0], [%1], 16;"
                             :: "r"(dst), "l"(D + (size_t)j * 1024) : "memory");
            }
        }
        asm volatile("cp.async.commit_group;" ::: "memory");
    }

    {
        // coalesced load of this thread's spectrum column (64B);
        // drop Im at DC/Nyquist (c2r semantics); Hermitian pack into xr/xi.
        int wfL = (tid <= 128) ? tid : 256 - tid;
        const float4* up = (const float4*)(ufrow + wfL * 8);
        float4 q0 = up[0], q1 = up[1], q2 = up[2], q3 = up[3];
        if (wfL == 0 || wfL == 128) {
            q0.y = 0.0f; q0.w = 0.0f; q1.y = 0.0f; q1.w = 0.0f;
            q2.y = 0.0f; q2.w = 0.0f; q3.y = 0.0f; q3.w = 0.0f;
        }
        float4 qs[4] = {q0, q1, q2, q3};
        int pt = PSW(tid);
        if (tid <= 128) {
#pragma unroll
            for (int p = 0; p < 4; p++) {
                xr[p * TS + pt] = qs[p].x - qs[p].w;   // A.x - B.y
                xi[p * TS + pt] = qs[p].y + qs[p].z;   // A.y + B.x
            }
        } else {
#pragma unroll
            for (int p = 0; p < 4; p++) {
                xr[p * TS + pt] = qs[p].x + qs[p].w;   // A.x + B.y
                xi[p * TS + pt] = qs[p].z - qs[p].y;   // B.x - A.y
            }
        }
        __syncthreads();
        fft4_stages<256>(xr, xi, yr, yi, tws, 4, tid, -1.0f);   // inverse (unnormalized)

        float gu[8], uu[8];
        int pw = PSW(w);
#pragma unroll
        for (int p = 0; p < 4; p++) {
            gu[2 * p]     = xr[p * TS + pw];
            gu[2 * p + 1] = xi[p * TS + pw];
        }
        {
            const float4* upu = (const float4*)(urow + w * 8);
            float4 a = upu[0], b = upu[1];
            uu[0] = a.x; uu[1] = a.y; uu[2] = a.z; uu[3] = a.w;
            uu[4] = b.x; uu[5] = b.y; uu[6] = b.z; uu[7] = b.w;
        }
        float tv[8];
#pragma unroll
        for (int j = 0; j < 8; j++) tv[j] = gu[j] - uu[j];
#pragma unroll
        for (int kk = 0; kk < 8; kk++) unew[kk] = 2.0f * uu[kk];

        // wait for prefetched G/D; each thread reads only its own slots.
        asm volatile("cp.async.wait_group 0;" ::: "memory");
#pragma unroll
        for (int j = 0; j < 8; j++) {
            float tj = tv[j];
            uint4 raw = (j < 4) ? sG[j * 256 + w]
                                : *reinterpret_cast<const uint4*>(G + (size_t)j * 1024);
            float2 g0 = __half22float2(u2h(raw.x));
            float2 g1 = __half22float2(u2h(raw.y));
            float2 g2 = __half22float2(u2h(raw.z));
            float2 g3 = __half22float2(u2h(raw.w));
            unew[0] = fmaf(tj, g0.x, unew[0]); unew[1] = fmaf(tj, g0.y, unew[1]);
            unew[2] = fmaf(tj, g1.x, unew[2]); unew[3] = fmaf(tj, g1.y, unew[3]);
            unew[4] = fmaf(tj, g2.x, unew[4]); unew[5] = fmaf(tj, g2.y, unew[5]);
            unew[6] = fmaf(tj, g3.x, unew[6]); unew[7] = fmaf(tj, g3.y, unew[7]);
        }
        if (MODE == 2) {
            float4 o0, o1;
            o0.x = gelu_t(unew[0] + bias[0]);
            o0.y = gelu_t(unew[1] + bias[1]);
            o0.z = gelu_t(unew[2] + bias[2]);
            o0.w = gelu_t(unew[3] + bias[3]);
            o1.x = gelu_t(unew[4] + bias[4]);
            o1.y = gelu_t(unew[5] + bias[5]);
            o1.z = gelu_t(unew[6] + bias[6]);
            o1.w = gelu_t(unew[7] + bias[7]);
            float4* op = (float4*)(outp + (size_t)row * 2048 + w * 8);
            op[0] = o0; op[1] = o1;
            return;
        }
        // MODE 1: persist u'
        {
            float4 o0, o1;
            o0.x = unew[0]; o0.y = unew[1]; o0.z = unew[2]; o0.w = unew[3];
            o1.x = unew[4]; o1.y = unew[5]; o1.z = unew[6]; o1.w = unew[7];
            float4* op = (float4*)(d_u + (size_t)row * 2048 + w * 8);
            op[0] = o0; op[1] = o1;
        }
    }

    // du = unew @ D ; pack ; forward FFT ; unpack rfft ; write Uf
    {
        float du[8];
#pragma unroll
        for (int kk = 0; kk < 8; kk++) du[kk] = 0.0f;
#pragma unroll
        for (int j = 0; j < 8; j++) {
            float uj = unew[j];
            uint4 raw = (j < 3) ? sD[j * 256 + w]
                                : *reinterpret_cast<const uint4*>(D + (size_t)j * 1024);
            float2 g0 = __half22float2(u2h(raw.x));
            float2 g1 = __half22float2(u2h(raw.y));
            float2 g2 = __half22float2(u2h(raw.z));
            float2 g3 = __half22float2(u2h(raw.w));
            du[0] = fmaf(uj, g0.x, du[0]); du[1] = fmaf(uj, g0.y, du[1]);
            du[2] = fmaf(uj, g1.x, du[2]); du[3] = fmaf(uj, g1.y, du[3]);
            du[4] = fmaf(uj, g2.x, du[4]); du[5] = fmaf(uj, g2.y, du[5]);
            du[6] = fmaf(uj, g3.x, du[6]); du[7] = fmaf(uj, g3.y, du[7]);
        }
        __syncthreads();   // all gu reads of xr/xi complete
        fwd_rfft_store(xr, xi, yr, yi, tws, du, ufrow, tid);
    }
}

// ---------------- column pass: FFT_H, filter matvec, IFFT_H (in-place on Uf) ---------
// 512 threads: one butterfly per thread per stage; matvec split by kk-half.
// (512,2): ~64 regs -> 2 blocks/SM (32 warps). Measured win in R14 (-9us total);
// R8's regression was the per-block n-loop, not the cap.
__global__ __launch_bounds__(512, 2) void k_col() {
    __shared__ __align__(16) float xr[8 * TS], xi[8 * TS], yr[8 * TS], yi[8 * TS];
    __shared__ float2 tws[128];
    int tid = threadIdx.x;
    int wf = blockIdx.x % 129;
    int n  = blockIdx.x / 129;
    fill_tw(tws, tid, 512);

    float2* base = d_uf + ((size_t)n * 256 * 129 + wf) * 8;  // + h*129*8 + c
    for (int it = 0; it < 4; it++) {
        int idx = it * 512 + tid;
        int h = idx >> 3, c = idx & 7;
        float2 v = base[(size_t)h * 129 * 8 + c];
        int a = c * TS + PSW(h);
        xr[a] = v.x;
        xi[a] = v.y;
    }
    __syncthreads();
    fft4_stages<512>(xr, xi, yr, yi, tws, 8, tid, 1.0f);     // forward along H

    int hf = tid & 255;
    int g  = tid >> 8;          // kk-half
    int ph = PSW(hf);
    float vr[4], vi[4];
#pragma unroll
    for (int q = 0; q < 4; q++) { vr[q] = 0.0f; vi[q] = 0.0f; }
    const __half2* F = d_filt + (((size_t)wf * 2 + g) * 8 * 256 + hf) * 4;
#pragma unroll
    for (int j = 0; j < 8; j++) {
        float zr = xr[j * TS + ph], zi = xi[j * TS + ph];
        uint4 fa = *reinterpret_cast<const uint4*>(F + (size_t)j * 1024);
        const unsigned* fu = &fa.x;
#pragma unroll
        for (int q = 0; q < 4; q++) {
            float2 f = __half22float2(u2h(fu[q]));
            vr[q] = fmaf(zr, f.x, fmaf(-zi, f.y, vr[q]));
            vi[q] = fmaf(zr, f.y, fmaf(zi, f.x, vi[q]));
        }
    }
    __syncthreads();
#pragma unroll
    for (int q = 0; q < 4; q++) {
        int kk = 4 * g + q;
        yr[kk * TS + ph] = vr[q];
        yi[kk * TS + ph] = vi[q];
    }
    __syncthreads();
    fft4_stages<512>(yr, yi, xr, xi, tws, 8, tid, -1.0f);    // inverse (unnormalized)

    const float inv = 1.0f / 65536.0f;  // both inverse-FFT norms (kept out of fp16 filt)
    for (int it = 0; it < 4; it++) {
        int idx = it * 512 + tid;
        int h = idx >> 3, c = idx & 7;
        int a = c * TS + PSW(h);
        base[(size_t)h * 129 * 8 + c] = make_float2(yr[a] * inv, yi[a] * inv);
    }
}

// ---------------- launch ----------------
extern "C" void kernel_launch(void* const* d_in, const int* in_sizes, int n_in,
                              void* d_out, int out_size) {
    const float* u    = (const float*)d_in[0];
    const float* kk   = (const float*)d_in[1];
    const float* gW[6];  for (int i = 0; i < 6; i++) gW[i]  = (const float*)d_in[2 + i];
    const float* dW[6];  for (int i = 0; i < 6; i++) dW[i]  = (const float*)d_in[8 + i];
    const float* frW[6]; for (int i = 0; i < 6; i++) frW[i] = (const float*)d_in[14 + i];
    const float* fiW[6]; for (int i = 0; i < 6; i++) fiW[i] = (const float*)d_in[20 + i];
    const float* bias = (const float*)d_in[26];
    float* out = (float*)d_out;

    // fused: G/D MLPs + iteration-0 row pass (du + rfft_W -> Uf)
    k_gdf<<<NROW, 256>>>(kk, u,
        gW[0], gW[1], gW[2], gW[3], gW[4], gW[5],
        dW[0], dW[1], dW[2], dW[3], dW[4], dW[5]);
    k_filt<<<129, 256>>>(
        frW[0], frW[1], frW[2], frW[3], frW[4], frW[5],
        fiW[0], fiW[1], fiW[2], fiW[3], fiW[4], fiW[5]);

    for (int it = 0; it < 4; it++) {
        k_col<<<4 * 129, 512>>>();
        if (it < 3) {
            k_row<1><<<NROW, 256>>>(it == 0 ? u : nullptr, nullptr, nullptr);
        } else {
            k_row<2><<<NROW, 256>>>(nullptr, bias, out);
        }
    }
}